// round 2
// baseline (speedup 1.0000x reference)
#include <cuda_runtime.h>
#include <math.h>
#include <stdint.h>

#define BATCH 8
#define KNNK 20
#define N1 4096
#define N2 1024
#define N3 256

// ======================= device scratch (static, no runtime alloc) =======================
__device__ float g_fo[BATCH * 4096 * 128];
__device__ float g_fa[BATCH * 4096 * 64];
__device__ float g_fb[BATCH * 4096 * 64];
__device__ int   g_nb[BATCH * 4096 * KNNK];
__device__ float g_ndirs[1024 * 3];
__device__ int   g_pool1[1024];
__device__ int   g_pool2[256];
__device__ float g_v2[BATCH * 1024 * 3];
__device__ float g_v3[BATCH * 256 * 3];
__device__ float g_act[BATCH * 256 * 64];
__device__ float g_bnm[64];
__device__ float g_bnv[64];
__device__ float g_asum[BATCH * 64];
__device__ float g_vlad[BATCH * 1024 * 64];
__device__ float g_cn[BATCH * 64];
__device__ float g_tn[BATCH];
__device__ float g_part[64 * BATCH * 1024];
__device__ float g_hidden[BATCH * 1024];
__device__ float g_vbn[BATCH * 1024];
__device__ float g_gpre[BATCH * 1024];

// Kahan compensated add — intrinsics prevent fast-math reassociation.
__device__ __forceinline__ void kadd(float& s, float& c, float v) {
    float y = __fadd_rn(v, -c);
    float t = __fadd_rn(s, y);
    c = __fadd_rn(__fadd_rn(t, -s), -y);
    s = t;
}

// ======================= pools upload (by-value params, capturable) =======================
struct PoolParams { int p1[1024]; int p2[256]; };

__global__ void set_pools_kernel(PoolParams pp) {
    for (int i = threadIdx.x; i < 1024; i += blockDim.x) g_pool1[i] = pp.p1[i];
    for (int i = threadIdx.x; i < 256;  i += blockDim.x) g_pool2[i] = pp.p2[i];
}

// ======================= KNN =======================
// top-20 smallest (dist, idx) lexicographic, excluding self.
// Distance arithmetic mirrors the reference: (sq_i + sq_j) - 2*dot, dot via fma chain.
#define KNN_TILE 256
__global__ void knn_kernel(const float* __restrict__ v, int N, int* __restrict__ nb) {
    int b = blockIdx.y;
    int i = blockIdx.x * blockDim.x + threadIdx.x;
    const float* vb = v + (size_t)b * N * 3;
    bool valid = i < N;
    float xi = 0, yi = 0, zi = 0, sqi = 0;
    if (valid) {
        xi = vb[i * 3]; yi = vb[i * 3 + 1]; zi = vb[i * 3 + 2];
        sqi = __fadd_rn(__fadd_rn(__fmul_rn(xi, xi), __fmul_rn(yi, yi)), __fmul_rn(zi, zi));
    }
    float bd[KNNK]; int bi_[KNNK];
#pragma unroll
    for (int t = 0; t < KNNK; t++) { bd[t] = INFINITY; bi_[t] = 0x7fffffff; }
    float worst_d = INFINITY; int worst_i = 0x7fffffff;

    __shared__ float sx[KNN_TILE], sy[KNN_TILE], sz[KNN_TILE], ss[KNN_TILE];
    for (int base = 0; base < N; base += KNN_TILE) {
        int cnt = min(KNN_TILE, N - base);
        for (int t = threadIdx.x; t < cnt; t += blockDim.x) {
            float X = vb[(base + t) * 3], Y = vb[(base + t) * 3 + 1], Z = vb[(base + t) * 3 + 2];
            sx[t] = X; sy[t] = Y; sz[t] = Z;
            ss[t] = __fadd_rn(__fadd_rn(__fmul_rn(X, X), __fmul_rn(Y, Y)), __fmul_rn(Z, Z));
        }
        __syncthreads();
        if (valid) {
            for (int t = 0; t < cnt; t++) {
                int j = base + t;
                float dot = fmaf(zi, sz[t], fmaf(yi, sy[t], __fmul_rn(xi, sx[t])));
                float d = __fadd_rn(__fadd_rn(sqi, ss[t]), -__fmul_rn(2.f, dot));
                if (j == i) continue;
                if (d < worst_d || (d == worst_d && j < worst_i)) {
                    int p = KNNK - 1;
                    while (p > 0 && (d < bd[p - 1] || (d == bd[p - 1] && j < bi_[p - 1]))) {
                        bd[p] = bd[p - 1]; bi_[p] = bi_[p - 1]; p--;
                    }
                    bd[p] = d; bi_[p] = j;
                    worst_d = bd[KNNK - 1]; worst_i = bi_[KNNK - 1];
                }
            }
        }
        __syncthreads();
    }
    if (valid) {
        for (int t = 0; t < KNNK; t++) nb[((size_t)b * N + i) * KNNK + t] = bi_[t];
    }
}

// ======================= direction normalization =======================
__global__ void norm_dirs_kernel(const float* __restrict__ dirs, int F, float* __restrict__ ndirs) {
    int f = blockIdx.x * blockDim.x + threadIdx.x;
    if (f >= F) return;
    float a = dirs[f], b = dirs[F + f], c = dirs[2 * F + f];
    float n = fmaxf(sqrtf(a * a + b * b + c * c), 1e-12f);
    ndirs[f * 3] = a / n; ndirs[f * 3 + 1] = b / n; ndirs[f * 3 + 2] = c / n;
}

// ======================= conv_surface =======================
__global__ void conv_surface_kernel(const float* __restrict__ v, const int* __restrict__ nb,
                                    const float* __restrict__ ndirs, float* __restrict__ fm,
                                    int N, int F) {
    int p = blockIdx.x; int b = p / N, n = p % N;
    __shared__ float sdx[KNNK], sdy[KNNK], sdz[KNNK];
    const float* vb = v + (size_t)b * N * 3;
    if (threadIdx.x < KNNK) {
        int j = nb[(size_t)p * KNNK + threadIdx.x];
        float dx = vb[j * 3] - vb[n * 3];
        float dy = vb[j * 3 + 1] - vb[n * 3 + 1];
        float dz = vb[j * 3 + 2] - vb[n * 3 + 2];
        float nm = fmaxf(sqrtf(dx * dx + dy * dy + dz * dz), 1e-12f);
        sdx[threadIdx.x] = dx / nm; sdy[threadIdx.x] = dy / nm; sdz[threadIdx.x] = dz / nm;
    }
    __syncthreads();
    for (int f = threadIdx.x; f < F; f += blockDim.x) {
        float d0 = ndirs[f * 3], d1 = ndirs[f * 3 + 1], d2 = ndirs[f * 3 + 2];
        float m = 0.f;
#pragma unroll
        for (int k = 0; k < KNNK; k++) {
            float t = fmaxf(sdx[k] * d0 + sdy[k] * d1 + sdz[k] * d2, 0.f);
            m = fmaxf(m, t);
        }
        fm[(size_t)p * F + f] = m;
    }
}

// ======================= conv_layer activation =======================
__global__ void conv_act_kernel(const float* __restrict__ v, const int* __restrict__ nb,
                                const float* __restrict__ ndirs, const float* __restrict__ fo,
                                float* __restrict__ out, int N, int OC, int relu_out) {
    int C = 2 * OC;
    int p = blockIdx.x; int b = p / N, n = p % N;
    __shared__ float sdx[KNNK], sdy[KNNK], sdz[KNNK];
    __shared__ int sj[KNNK];
    const float* vb = v + (size_t)b * N * 3;
    if (threadIdx.x < KNNK) {
        int j = nb[(size_t)p * KNNK + threadIdx.x];
        sj[threadIdx.x] = b * N + j;
        float dx = vb[j * 3] - vb[n * 3];
        float dy = vb[j * 3 + 1] - vb[n * 3 + 1];
        float dz = vb[j * 3 + 2] - vb[n * 3 + 2];
        float nm = fmaxf(sqrtf(dx * dx + dy * dy + dz * dz), 1e-12f);
        sdx[threadIdx.x] = dx / nm; sdy[threadIdx.x] = dy / nm; sdz[threadIdx.x] = dz / nm;
    }
    __syncthreads();
    for (int f = threadIdx.x; f < OC; f += blockDim.x) {
        float d0 = ndirs[f * 3], d1 = ndirs[f * 3 + 1], d2 = ndirs[f * 3 + 2];
        float m = -INFINITY;
#pragma unroll
        for (int k = 0; k < KNNK; k++) {
            float th = fmaxf(sdx[k] * d0 + sdy[k] * d1 + sdz[k] * d2, 0.f);
            float fs = fo[(size_t)sj[k] * C + OC + f];
            m = fmaxf(m, th * fs);
        }
        float val = fo[(size_t)p * C + f] + m;
        if (relu_out) val = fmaxf(val, 0.f);
        out[(size_t)p * OC + f] = val;
    }
}

// ======================= gather + max over neighbors =======================
__global__ void gather_max_kernel(const float* __restrict__ fm, const int* __restrict__ nb,
                                  float* __restrict__ out, int N, int F) {
    int idx = blockIdx.x * blockDim.x + threadIdx.x;
    int tot = BATCH * N * F;
    if (idx >= tot) return;
    int f = idx % F; int p = idx / F; int b = p / N;
    const int* nbp = nb + (size_t)p * KNNK;
    float m = -INFINITY;
#pragma unroll
    for (int k = 0; k < KNNK; k++) {
        m = fmaxf(m, fm[((size_t)b * N + nbp[k]) * F + f]);
    }
    out[idx] = m;
}

// ======================= gather rows (pool selection) =======================
__global__ void gather_rows_kernel(const float* __restrict__ in, const int* __restrict__ pool,
                                   float* __restrict__ out, int Nin, int Nout, int F) {
    int idx = blockIdx.x * blockDim.x + threadIdx.x;
    int tot = BATCH * Nout * F;
    if (idx >= tot) return;
    int f = idx % F; int r = idx / F; int b = r / Nout; int pp = r % Nout;
    out[idx] = in[((size_t)b * Nin + pool[pp]) * F + f];
}

// ======================= tiled fp32 GEMM (plain) =======================
__global__ void gemm_kernel(const float* __restrict__ A, const float* __restrict__ B,
                            const float* __restrict__ bias, float* __restrict__ C,
                            int M, int K, int N) {
    __shared__ float As[16][65];
    __shared__ float Bs[16][65];
    int row0 = blockIdx.y * 64, col0 = blockIdx.x * 64;
    int tid = threadIdx.x;
    int tx = tid % 16, ty = tid / 16;
    float acc[4][4] = {};
    for (int k0 = 0; k0 < K; k0 += 16) {
        for (int t = tid; t < 64 * 16; t += 256) {
            int r = t / 16, c = t % 16;
            int gr = row0 + r, gc = k0 + c;
            As[c][r] = (gr < M && gc < K) ? A[(size_t)gr * K + gc] : 0.f;
        }
        for (int t = tid; t < 16 * 64; t += 256) {
            int r = t / 64, c = t % 64;
            int gr = k0 + r, gc = col0 + c;
            Bs[r][c] = (gr < K && gc < N) ? B[(size_t)gr * N + gc] : 0.f;
        }
        __syncthreads();
#pragma unroll
        for (int kk = 0; kk < 16; kk++) {
            float a[4], bb[4];
#pragma unroll
            for (int i = 0; i < 4; i++) a[i] = As[kk][ty * 4 + i];
#pragma unroll
            for (int j = 0; j < 4; j++) bb[j] = Bs[kk][tx * 4 + j];
#pragma unroll
            for (int i = 0; i < 4; i++)
#pragma unroll
                for (int j = 0; j < 4; j++) acc[i][j] += a[i] * bb[j];
        }
        __syncthreads();
    }
    for (int i = 0; i < 4; i++) {
        int gr = row0 + ty * 4 + i;
        if (gr >= M) continue;
        for (int j = 0; j < 4; j++) {
            int gc = col0 + tx * 4 + j;
            if (gc < N) C[(size_t)gr * N + gc] = acc[i][j] + (bias ? bias[gc] : 0.f);
        }
    }
}

// ======================= tiled fp32 GEMM (Kahan accumulation; for NetVLAD cluster GEMM) ===
__global__ void gemm_kahan_kernel(const float* __restrict__ A, const float* __restrict__ B,
                                  float* __restrict__ C, int M, int K, int N) {
    __shared__ float As[16][65];
    __shared__ float Bs[16][65];
    int row0 = blockIdx.y * 64, col0 = blockIdx.x * 64;
    int tid = threadIdx.x;
    int tx = tid % 16, ty = tid / 16;
    float acc[4][4] = {}; float cmp[4][4] = {};
    for (int k0 = 0; k0 < K; k0 += 16) {
        for (int t = tid; t < 64 * 16; t += 256) {
            int r = t / 16, c = t % 16;
            int gr = row0 + r, gc = k0 + c;
            As[c][r] = (gr < M && gc < K) ? A[(size_t)gr * K + gc] : 0.f;
        }
        for (int t = tid; t < 16 * 64; t += 256) {
            int r = t / 64, c = t % 64;
            int gr = k0 + r, gc = col0 + c;
            Bs[r][c] = (gr < K && gc < N) ? B[(size_t)gr * N + gc] : 0.f;
        }
        __syncthreads();
#pragma unroll
        for (int kk = 0; kk < 16; kk++) {
            float a[4], bb[4];
#pragma unroll
            for (int i = 0; i < 4; i++) a[i] = As[kk][ty * 4 + i];
#pragma unroll
            for (int j = 0; j < 4; j++) bb[j] = Bs[kk][tx * 4 + j];
#pragma unroll
            for (int i = 0; i < 4; i++)
#pragma unroll
                for (int j = 0; j < 4; j++) kadd(acc[i][j], cmp[i][j], __fmul_rn(a[i], bb[j]));
        }
        __syncthreads();
    }
    for (int i = 0; i < 4; i++) {
        int gr = row0 + ty * 4 + i;
        if (gr >= M) continue;
        for (int j = 0; j < 4; j++) {
            int gc = col0 + tx * 4 + j;
            if (gc < N) C[(size_t)gr * N + gc] = acc[i][j];
        }
    }
}

// ======================= GeM pooling =======================
__global__ void gem_kernel(const float* __restrict__ fm4, const float* __restrict__ gem_p,
                           float* __restrict__ y) {
    int idx = blockIdx.x * blockDim.x + threadIdx.x;
    if (idx >= BATCH * 1024) return;
    int b = idx / 1024, c = idx % 1024;
    float p = gem_p[0];
    float s = 0.f, sc = 0.f;
    for (int n = 0; n < N3; n++) {
        float f = fmaxf(fm4[((size_t)b * N3 + n) * 1024 + c], 1e-6f);
        kadd(s, sc, powf(f, p));
    }
    s /= (float)N3;
    y[idx] = powf(s, 1.f / p);
}

// ======================= NetVLAD kernels =======================
// Two-pass mean/var (matches x.var semantics), Kahan per-thread + double tree merge.
__global__ void bn1_stats_kernel(const float* __restrict__ act, float* __restrict__ mean,
                                 float* __restrict__ var, int rows) {
    int k = blockIdx.x;
    __shared__ double sd[256];
    float a = 0.f, ac = 0.f;
    for (int r = threadIdx.x; r < rows; r += 256) kadd(a, ac, act[(size_t)r * 64 + k]);
    sd[threadIdx.x] = (double)a; __syncthreads();
    for (int s = 128; s > 0; s >>= 1) {
        if (threadIdx.x < s) sd[threadIdx.x] += sd[threadIdx.x + s];
        __syncthreads();
    }
    float m = (float)(sd[0] / rows);
    __syncthreads();
    float q = 0.f, qc = 0.f;
    for (int r = threadIdx.x; r < rows; r += 256) {
        float d = __fadd_rn(act[(size_t)r * 64 + k], -m);
        kadd(q, qc, __fmul_rn(d, d));
    }
    sd[threadIdx.x] = (double)q; __syncthreads();
    for (int s = 128; s > 0; s >>= 1) {
        if (threadIdx.x < s) sd[threadIdx.x] += sd[threadIdx.x + s];
        __syncthreads();
    }
    if (threadIdx.x == 0) { mean[k] = m; var[k] = (float)(sd[0] / rows); }
}

__global__ void bn_softmax_kernel(float* __restrict__ act, const float* __restrict__ mean,
                                  const float* __restrict__ var, const float* __restrict__ g,
                                  const float* __restrict__ bb) {
    int r = blockIdx.x; int k = threadIdx.x;
    __shared__ float sv[64];
    float v = (act[(size_t)r * 64 + k] - mean[k]) * rsqrtf(var[k] + 1e-5f) * g[k] + bb[k];
    sv[k] = v; __syncthreads();
    float mx = -INFINITY;
    for (int t = 0; t < 64; t++) mx = fmaxf(mx, sv[t]);
    float e = expf(v - mx);
    __syncthreads(); sv[k] = e; __syncthreads();
    float s = 0.f, sc = 0.f;
    for (int t = 0; t < 64; t++) kadd(s, sc, sv[t]);
    act[(size_t)r * 64 + k] = e / s;
}

__global__ void asum_kernel(const float* __restrict__ act, float* __restrict__ asum) {
    int t = blockIdx.x * blockDim.x + threadIdx.x;
    if (t >= BATCH * 64) return;
    int b = t / 64, k = t % 64;
    float s = 0.f, sc = 0.f;
    for (int m = 0; m < N3; m++) kadd(s, sc, act[((size_t)b * N3 + m) * 64 + k]);
    asum[t] = s;
}

__global__ void vlad_kernel(const float* __restrict__ act, const float* __restrict__ xv,
                            const float* __restrict__ asum, const float* __restrict__ cw2,
                            float* __restrict__ vlad) {
    int f = blockIdx.x; int b = blockIdx.y; int k = threadIdx.x;
    float s = 0.f, sc = 0.f;
    for (int m = 0; m < N3; m++) {
        kadd(s, sc, __fmul_rn(act[((size_t)b * N3 + m) * 64 + k], xv[((size_t)b * N3 + m) * 1024 + f]));
    }
    s = __fadd_rn(s, -__fmul_rn(asum[b * 64 + k], cw2[(size_t)f * 64 + k]));
    vlad[((size_t)b * 1024 + f) * 64 + k] = s;
}

__global__ void colnorm_kernel(const float* __restrict__ vlad, float* __restrict__ cn) {
    int b = blockIdx.x; int tid = threadIdx.x;
    int k = tid % 64, grp = tid / 64;  // 16 groups
    float s = 0.f, sc = 0.f;
    for (int f = grp; f < 1024; f += 16) {
        float v = vlad[((size_t)b * 1024 + f) * 64 + k];
        kadd(s, sc, __fmul_rn(v, v));
    }
    __shared__ double sm[1024];
    sm[tid] = (double)s; __syncthreads();
    if (grp == 0) {
        double t = 0.0;
        for (int g2 = 0; g2 < 16; g2++) t += sm[g2 * 64 + k];
        cn[b * 64 + k] = (float)t;
    }
}

__global__ void tn_kernel(const float* __restrict__ cn, float* __restrict__ tn) {
    int b = threadIdx.x;
    if (b >= BATCH) return;
    double s = 0.0;
    for (int k = 0; k < 64; k++) {
        float c = cn[b * 64 + k];
        float d = fmaxf(sqrtf(c), 1e-12f);
        float vn = c / (d * d);
        s += (double)vn;
    }
    tn[b] = (float)s;
}

__global__ void vnorm_kernel(float* __restrict__ vlad, const float* __restrict__ cn,
                             const float* __restrict__ tn) {
    int idx = blockIdx.x * blockDim.x + threadIdx.x;
    if (idx >= BATCH * 1024 * 64) return;
    int k = idx % 64; int b = idx / (1024 * 64);
    float d1 = fmaxf(sqrtf(cn[b * 64 + k]), 1e-12f);
    float d2 = fmaxf(sqrtf(tn[b]), 1e-12f);
    vlad[idx] = vlad[idx] / d1 / d2;
}

// skinny GEMM with Kahan: part[chunk][b][j] = sum_{i in chunk} A[b][i]*W[i][j]
#define SKC 1024
__global__ void skinny8_kernel(const float* __restrict__ A, const float* __restrict__ W,
                               float* __restrict__ part, int K, int N) {
    int j = blockIdx.x * 256 + threadIdx.x;
    int k0 = blockIdx.y * SKC;
    int len = min(SKC, K - k0);
    __shared__ float xs[BATCH * SKC];
    for (int t = threadIdx.x; t < BATCH * len; t += 256) {
        int bb = t / len; int ii = t % len;
        xs[bb * len + ii] = A[(size_t)bb * K + k0 + ii];
    }
    __syncthreads();
    if (j < N) {
        float acc[BATCH] = {}; float cmp[BATCH] = {};
        for (int i = 0; i < len; i++) {
            float w = W[(size_t)(k0 + i) * N + j];
#pragma unroll
            for (int bb = 0; bb < BATCH; bb++) kadd(acc[bb], cmp[bb], __fmul_rn(xs[bb * len + i], w));
        }
#pragma unroll
        for (int bb = 0; bb < BATCH; bb++) {
            part[(size_t)blockIdx.y * BATCH * N + bb * N + j] = acc[bb];
        }
    }
}

__global__ void reduce_chunks_kernel(const float* __restrict__ part, float* __restrict__ out,
                                     int nchunks, int tot) {
    int idx = blockIdx.x * blockDim.x + threadIdx.x;
    if (idx >= tot) return;
    float s = 0.f, sc = 0.f;
    for (int c = 0; c < nchunks; c++) kadd(s, sc, part[(size_t)c * tot + idx]);
    out[idx] = s;
}

__global__ void bn8_kernel(const float* __restrict__ in, const float* __restrict__ g,
                           const float* __restrict__ bb, float* __restrict__ out, int N) {
    int j = blockIdx.x * blockDim.x + threadIdx.x;
    if (j >= N) return;
    double m = 0.0;
    for (int b = 0; b < BATCH; b++) m += (double)in[b * N + j];
    m /= BATCH;
    double q = 0.0;
    for (int b = 0; b < BATCH; b++) { double d = (double)in[b * N + j] - m; q += d * d; }
    q /= BATCH;
    float mf = (float)m;
    float inv = rsqrtf((float)q + 1e-5f);
    for (int b = 0; b < BATCH; b++) out[b * N + j] = (in[b * N + j] - mf) * inv * g[j] + bb[j];
}

__global__ void gate_final_kernel(const float* __restrict__ vbn, const float* __restrict__ gpre,
                                  const float* __restrict__ gg, const float* __restrict__ gb,
                                  float* __restrict__ desc) {
    int j = blockIdx.x * blockDim.x + threadIdx.x;
    if (j >= 1024) return;
    double m = 0.0;
    for (int b = 0; b < BATCH; b++) m += (double)gpre[b * 1024 + j];
    m /= BATCH;
    double q = 0.0;
    for (int b = 0; b < BATCH; b++) { double d = (double)gpre[b * 1024 + j] - m; q += d * d; }
    q /= BATCH;
    float mf = (float)m;
    float inv = rsqrtf((float)q + 1e-5f);
    for (int b = 0; b < BATCH; b++) {
        float z = (gpre[b * 1024 + j] - mf) * inv * gg[j] + gb[j];
        float s = 1.f / (1.f + expf(-z));
        desc[b * 1024 + j] = vbn[b * 1024 + j] * s;
    }
}

// ======================= host: numpy-compatible MT19937 pools =======================
struct MTState { uint32_t mt[624]; int idx; };

static void mt_seed(MTState& s, uint32_t seed) {
    for (int p = 0; p < 624; p++) {
        s.mt[p] = seed;
        seed = 1812433253u * (seed ^ (seed >> 30)) + (uint32_t)p + 1u;
    }
    s.idx = 624;
}
static uint32_t mt_next(MTState& s) {
    if (s.idx >= 624) {
        for (int i = 0; i < 624; i++) {
            uint32_t y = (s.mt[i] & 0x80000000u) | (s.mt[(i + 1) % 624] & 0x7fffffffu);
            uint32_t v = s.mt[(i + 397) % 624] ^ (y >> 1);
            if (y & 1u) v ^= 0x9908b0dfu;
            s.mt[i] = v;
        }
        s.idx = 0;
    }
    uint32_t y = s.mt[s.idx++];
    y ^= y >> 11;
    y ^= (y << 7) & 0x9d2c5680u;
    y ^= (y << 15) & 0xefc60000u;
    y ^= y >> 18;
    return y;
}
static uint32_t rk_interval(MTState& s, uint32_t mx) {
    if (mx == 0) return 0;
    uint32_t mask = mx;
    mask |= mask >> 1; mask |= mask >> 2; mask |= mask >> 4;
    mask |= mask >> 8; mask |= mask >> 16;
    uint32_t v;
    while ((v = (mt_next(s) & mask)) > mx) {}
    return v;
}
static void np_permutation(uint32_t seed, int n, int* out) {
    for (int i = 0; i < n; i++) out[i] = i;
    MTState s; mt_seed(s, seed);
    for (int i = n - 1; i >= 1; i--) {
        uint32_t j = rk_interval(s, (uint32_t)i);
        int t = out[i]; out[i] = out[(int)j]; out[(int)j] = t;
    }
}

// ======================= launch =======================
extern "C" void kernel_launch(void* const* d_in, const int* in_sizes, int n_in,
                              void* d_out, int out_size) {
    const float* x         = (const float*)d_in[0];
    const float* dir0      = (const float*)d_in[1];
    const float* W1        = (const float*)d_in[2];
    const float* b1        = (const float*)d_in[3];
    const float* dir1      = (const float*)d_in[4];
    const float* W2        = (const float*)d_in[5];
    const float* b2        = (const float*)d_in[6];
    const float* dir2      = (const float*)d_in[7];
    const float* W3        = (const float*)d_in[8];
    const float* b3        = (const float*)d_in[9];
    const float* dir3      = (const float*)d_in[10];
    const float* W4        = (const float*)d_in[11];
    const float* b4        = (const float*)d_in[12];
    const float* dir4      = (const float*)d_in[13];
    const float* gem_p     = (const float*)d_in[14];
    const float* cluster_w = (const float*)d_in[15];
    const float* cluster_w2= (const float*)d_in[16];
    const float* hidden_w  = (const float*)d_in[17];
    const float* bn1_g     = (const float*)d_in[18];
    const float* bn1_b     = (const float*)d_in[19];
    const float* bn2_g     = (const float*)d_in[20];
    const float* bn2_b     = (const float*)d_in[21];
    const float* gating_w  = (const float*)d_in[22];
    const float* gbn_g     = (const float*)d_in[23];
    const float* gbn_b     = (const float*)d_in[24];
    float* out = (float*)d_out;

    float *fo, *fa, *fb, *ndirs, *v2, *v3, *act, *bnm, *bnv, *asum, *vlad, *cn, *tn, *part, *hidden, *vbn, *gpre;
    int *nb, *pool1, *pool2;
    cudaGetSymbolAddress((void**)&fo, g_fo);
    cudaGetSymbolAddress((void**)&fa, g_fa);
    cudaGetSymbolAddress((void**)&fb, g_fb);
    cudaGetSymbolAddress((void**)&nb, g_nb);
    cudaGetSymbolAddress((void**)&ndirs, g_ndirs);
    cudaGetSymbolAddress((void**)&pool1, g_pool1);
    cudaGetSymbolAddress((void**)&pool2, g_pool2);
    cudaGetSymbolAddress((void**)&v2, g_v2);
    cudaGetSymbolAddress((void**)&v3, g_v3);
    cudaGetSymbolAddress((void**)&act, g_act);
    cudaGetSymbolAddress((void**)&bnm, g_bnm);
    cudaGetSymbolAddress((void**)&bnv, g_bnv);
    cudaGetSymbolAddress((void**)&asum, g_asum);
    cudaGetSymbolAddress((void**)&vlad, g_vlad);
    cudaGetSymbolAddress((void**)&cn, g_cn);
    cudaGetSymbolAddress((void**)&tn, g_tn);
    cudaGetSymbolAddress((void**)&part, g_part);
    cudaGetSymbolAddress((void**)&hidden, g_hidden);
    cudaGetSymbolAddress((void**)&vbn, g_vbn);
    cudaGetSymbolAddress((void**)&gpre, g_gpre);

    static PoolParams pp;
    {
        static int perm1[N1];
        static int perm2[N2];
        np_permutation(1u, N1, perm1);
        np_permutation(2u, N2, perm2);
        for (int i = 0; i < 1024; i++) pp.p1[i] = perm1[i];
        for (int i = 0; i < 256;  i++) pp.p2[i] = perm2[i];
    }
    set_pools_kernel<<<1, 256>>>(pp);

    // ================= stage 1 (4096 pts) =================
    knn_kernel<<<dim3((N1 + 255) / 256, BATCH), 256>>>(x, N1, nb);

    norm_dirs_kernel<<<1, 128>>>(dir0, 32, ndirs);
    conv_surface_kernel<<<BATCH * N1, 128>>>(x, nb, ndirs, fa, N1, 32);

    gemm_kernel<<<dim3(2, (BATCH * N1 + 63) / 64), 256>>>(fa, W1, b1, fo, BATCH * N1, 32, 128);
    norm_dirs_kernel<<<1, 128>>>(dir1, 64, ndirs);
    conv_act_kernel<<<BATCH * N1, 128>>>(x, nb, ndirs, fo, fb, N1, 64, 1);

    {
        int tot = BATCH * N1 * 64;
        gather_max_kernel<<<(tot + 255) / 256, 256>>>(fb, nb, fa, N1, 64);
    }
    {
        int tot = BATCH * N2 * 64;
        gather_rows_kernel<<<(tot + 255) / 256, 256>>>(fa, pool1, fb, N1, N2, 64);
        int totv = BATCH * N2 * 3;
        gather_rows_kernel<<<(totv + 255) / 256, 256>>>(x, pool1, v2, N1, N2, 3);
    }

    // ================= stage 2 (1024 pts) =================
    knn_kernel<<<dim3((N2 + 255) / 256, BATCH), 256>>>(v2, N2, nb);

    gemm_kernel<<<dim3(4, (BATCH * N2 + 63) / 64), 256>>>(fb, W2, b2, fo, BATCH * N2, 64, 256);
    norm_dirs_kernel<<<1, 128>>>(dir2, 128, ndirs);
    conv_act_kernel<<<BATCH * N2, 128>>>(v2, nb, ndirs, fo, fa, N2, 128, 1);

    gemm_kernel<<<dim3(8, (BATCH * N2 + 63) / 64), 256>>>(fa, W3, b3, fo, BATCH * N2, 128, 512);
    norm_dirs_kernel<<<2, 128>>>(dir3, 256, ndirs);
    conv_act_kernel<<<BATCH * N2, 256>>>(v2, nb, ndirs, fo, fb, N2, 256, 1);

    {
        int tot = BATCH * N2 * 256;
        gather_max_kernel<<<(tot + 255) / 256, 256>>>(fb, nb, fa, N2, 256);
    }
    {
        int tot = BATCH * N3 * 256;
        gather_rows_kernel<<<(tot + 255) / 256, 256>>>(fa, pool2, fb, N2, N3, 256);
        int totv = BATCH * N3 * 3;
        gather_rows_kernel<<<(totv + 255) / 256, 256>>>(v2, pool2, v3, N2, N3, 3);
    }

    // ================= stage 3 (256 pts) =================
    knn_kernel<<<dim3(1, BATCH), 256>>>(v3, N3, nb);

    gemm_kernel<<<dim3(32, (BATCH * N3 + 63) / 64), 256>>>(fb, W4, b4, fo, BATCH * N3, 256, 2048);
    norm_dirs_kernel<<<8, 128>>>(dir4, 1024, ndirs);
    conv_act_kernel<<<BATCH * N3, 256>>>(v3, nb, ndirs, fo, fa, N3, 1024, 0);

    // ---- GeM -> y ----
    gem_kernel<<<(BATCH * 1024 + 255) / 256, 256>>>(fa, gem_p, out);

    // ================= NetVLAD =================
    gemm_kahan_kernel<<<dim3(1, (BATCH * N3 + 63) / 64), 256>>>(fa, cluster_w, act, BATCH * N3, 1024, 64);
    bn1_stats_kernel<<<64, 256>>>(act, bnm, bnv, BATCH * N3);
    bn_softmax_kernel<<<BATCH * N3, 64>>>(act, bnm, bnv, bn1_g, bn1_b);
    asum_kernel<<<2, 256>>>(act, asum);
    vlad_kernel<<<dim3(1024, BATCH), 64>>>(act, fa, asum, cluster_w2, vlad);
    colnorm_kernel<<<BATCH, 1024>>>(vlad, cn);
    tn_kernel<<<1, 32>>>(cn, tn);
    vnorm_kernel<<<(BATCH * 1024 * 64 + 255) / 256, 256>>>(vlad, cn, tn);

    // hidden: (8 x 65536) @ (65536 x 1024)
    skinny8_kernel<<<dim3(4, 64), 256>>>(vlad, hidden_w, part, 65536, 1024);
    reduce_chunks_kernel<<<(BATCH * 1024 + 255) / 256, 256>>>(part, hidden, 64, BATCH * 1024);
    bn8_kernel<<<4, 256>>>(hidden, bn2_g, bn2_b, vbn, 1024);

    // gating: (8 x 1024) @ (1024 x 1024)
    skinny8_kernel<<<dim3(4, 1), 256>>>(vbn, gating_w, part, 1024, 1024);
    reduce_chunks_kernel<<<(BATCH * 1024 + 255) / 256, 256>>>(part, gpre, 1, BATCH * 1024);
    gate_final_kernel<<<4, 256>>>(vbn, gpre, gbn_g, gbn_b, out + BATCH * 1024);
}

// round 3
// speedup vs baseline: 1.7631x; 1.7631x over previous
#include <cuda_runtime.h>
#include <math.h>
#include <stdint.h>

#define BATCH 8
#define KNNK 20
#define N1 4096
#define N2 1024
#define N3 256

// ======================= device scratch =======================
__device__ float g_fo[BATCH * 4096 * 128];
__device__ float g_fa[BATCH * 4096 * 64];
__device__ float g_fb[BATCH * 4096 * 64];
__device__ int   g_nb[BATCH * 4096 * KNNK];
__device__ float g_ndirs[1504 * 3];
__device__ int   g_pool1[1024];
__device__ int   g_pool2[256];
__device__ float g_v2[BATCH * 1024 * 3];
__device__ float g_v3[BATCH * 256 * 3];
__device__ float g_act[BATCH * 256 * 64];
__device__ float g_bnm[64];
__device__ float g_bnv[64];
__device__ float g_asum[BATCH * 64];
__device__ float g_vlad[BATCH * 1024 * 64];
__device__ float g_cn[BATCH * 64];
__device__ float g_tn[BATCH];
__device__ float g_part[64 * BATCH * 1024];
__device__ float g_hidden[BATCH * 1024];
__device__ float g_vbn[BATCH * 1024];
__device__ float g_gpre[BATCH * 1024];

__device__ __forceinline__ void kadd(float& s, float& c, float v) {
    float y = __fadd_rn(v, -c);
    float t = __fadd_rn(s, y);
    c = __fadd_rn(__fadd_rn(t, -s), -y);
    s = t;
}

// ======================= pools =======================
struct PoolParams { int p1[1024]; int p2[256]; };

__global__ void set_pools_kernel(PoolParams pp) {
    for (int i = threadIdx.x; i < 1024; i += blockDim.x) g_pool1[i] = pp.p1[i];
    for (int i = threadIdx.x; i < 256;  i += blockDim.x) g_pool2[i] = pp.p2[i];
}

// ======================= all direction normalizations upfront =======================
// segments: dir0[32]@0, dir1[64]@32, dir2[128]@96, dir3[256]@224, dir4[1024]@480
__global__ void norm_dirs_all_kernel(const float* __restrict__ d0, const float* __restrict__ d1,
                                     const float* __restrict__ d2, const float* __restrict__ d3,
                                     const float* __restrict__ d4) {
    int t = blockIdx.x * blockDim.x + threadIdx.x;
    const float* src; int F, off, f;
    if      (t < 32)   { src = d0; F = 32;   off = 0;   f = t; }
    else if (t < 96)   { src = d1; F = 64;   off = 32;  f = t - 32; }
    else if (t < 224)  { src = d2; F = 128;  off = 96;  f = t - 96; }
    else if (t < 480)  { src = d3; F = 256;  off = 224; f = t - 224; }
    else if (t < 1504) { src = d4; F = 1024; off = 480; f = t - 480; }
    else return;
    float a = src[f], b = src[F + f], c = src[2 * F + f];
    float n = fmaxf(sqrtf(a * a + b * b + c * c), 1e-12f);
    g_ndirs[(off + f) * 3]     = a / n;
    g_ndirs[(off + f) * 3 + 1] = b / n;
    g_ndirs[(off + f) * 3 + 2] = c / n;
}

// ======================= KNN: register-resident max-replace top-20 =======================
#define KNN_TILE 128
__global__ void knn_kernel(const float* __restrict__ v, int N, int* __restrict__ nb) {
    int b = blockIdx.y;
    int i = blockIdx.x * blockDim.x + threadIdx.x;
    const float* vb = v + (size_t)b * N * 3;
    float xi = vb[i * 3], yi = vb[i * 3 + 1], zi = vb[i * 3 + 2];
    float sqi = __fadd_rn(__fadd_rn(__fmul_rn(xi, xi), __fmul_rn(yi, yi)), __fmul_rn(zi, zi));

    float bd[KNNK]; int bi_[KNNK];
#pragma unroll
    for (int t = 0; t < KNNK; t++) { bd[t] = INFINITY; bi_[t] = 0x7fffffff; }
    float worst_d = INFINITY; int worst_i = 0x7fffffff; int wslot = 0;

    __shared__ float4 sp[KNN_TILE];
    for (int base = 0; base < N; base += KNN_TILE) {
        {
            int t = threadIdx.x;
            float X = vb[(base + t) * 3], Y = vb[(base + t) * 3 + 1], Z = vb[(base + t) * 3 + 2];
            float S = __fadd_rn(__fadd_rn(__fmul_rn(X, X), __fmul_rn(Y, Y)), __fmul_rn(Z, Z));
            sp[t] = make_float4(X, Y, Z, S);
        }
        __syncthreads();
        for (int t = 0; t < KNN_TILE; t++) {
            int j = base + t;
            float4 q = sp[t];
            float dot = fmaf(zi, q.z, fmaf(yi, q.y, __fmul_rn(xi, q.x)));
            float d = __fadd_rn(__fadd_rn(sqi, q.w), -__fmul_rn(2.f, dot));
            if (j == i) continue;
            if (d < worst_d || (d == worst_d && j < worst_i)) {
#pragma unroll
                for (int s = 0; s < KNNK; s++) if (s == wslot) { bd[s] = d; bi_[s] = j; }
                worst_d = bd[0]; worst_i = bi_[0]; wslot = 0;
#pragma unroll
                for (int s = 1; s < KNNK; s++) {
                    bool g = (bd[s] > worst_d) || (bd[s] == worst_d && bi_[s] > worst_i);
                    if (g) { worst_d = bd[s]; worst_i = bi_[s]; wslot = s; }
                }
            }
        }
        __syncthreads();
    }
#pragma unroll
    for (int t = 0; t < KNNK; t++) nb[((size_t)b * N + i) * KNNK + t] = bi_[t];
}

// ======================= conv_surface: 256 threads, G points/block =======================
__global__ void conv_surface_kernel(const float* __restrict__ v, const int* __restrict__ nb,
                                    const float* __restrict__ ndirs, float* __restrict__ fm,
                                    int N, int OC, int G) {
    __shared__ float sdx[160], sdy[160], sdz[160];
    int p0 = blockIdx.x * G;
    int t = threadIdx.x;
    if (t < G * KNNK) {
        int g = t / KNNK, k = t % KNNK;
        int p = p0 + g; int b = p / N; int n = p % N;
        const float* vb = v + (size_t)b * N * 3;
        int j = nb[(size_t)p * KNNK + k];
        float dx = vb[j * 3] - vb[n * 3];
        float dy = vb[j * 3 + 1] - vb[n * 3 + 1];
        float dz = vb[j * 3 + 2] - vb[n * 3 + 2];
        float nm = fmaxf(sqrtf(dx * dx + dy * dy + dz * dz), 1e-12f);
        sdx[t] = dx / nm; sdy[t] = dy / nm; sdz[t] = dz / nm;
    }
    __syncthreads();
    int OCc = 256 / G;
    int g = t / OCc, f = t % OCc;
    int p = p0 + g;
    float d0 = ndirs[f * 3], d1 = ndirs[f * 3 + 1], d2 = ndirs[f * 3 + 2];
    float m = 0.f;
    int kb = g * KNNK;
#pragma unroll
    for (int k = 0; k < KNNK; k++) {
        float th = fmaxf(sdx[kb + k] * d0 + sdy[kb + k] * d1 + sdz[kb + k] * d2, 0.f);
        m = fmaxf(m, th);
    }
    fm[(size_t)p * OC + f] = m;
}

// ======================= conv_layer activation: 256 threads, G points/block =======================
__global__ void conv_act_kernel(const float* __restrict__ v, const int* __restrict__ nb,
                                const float* __restrict__ ndirs, const float* __restrict__ fo,
                                float* __restrict__ out, int N, int OC, int G, int relu_out) {
    int C = 2 * OC;
    __shared__ float sdx[160], sdy[160], sdz[160];
    __shared__ int sj[160];
    int p0 = blockIdx.x * G;
    int t = threadIdx.x;
    if (t < G * KNNK) {
        int g = t / KNNK, k = t % KNNK;
        int p = p0 + g; int b = p / N; int n = p % N;
        const float* vb = v + (size_t)b * N * 3;
        int j = nb[(size_t)p * KNNK + k];
        sj[t] = b * N + j;
        float dx = vb[j * 3] - vb[n * 3];
        float dy = vb[j * 3 + 1] - vb[n * 3 + 1];
        float dz = vb[j * 3 + 2] - vb[n * 3 + 2];
        float nm = fmaxf(sqrtf(dx * dx + dy * dy + dz * dz), 1e-12f);
        sdx[t] = dx / nm; sdy[t] = dy / nm; sdz[t] = dz / nm;
    }
    __syncthreads();
    int OCc = 256 / G;         // = min(OC, 256)
    int g = t / OCc, fb = t % OCc;
    int p = p0 + g;
    int kb = g * KNNK;
    const float* forow = fo + (size_t)p * C;
    for (int f = fb; f < OC; f += OCc) {
        float d0 = ndirs[f * 3], d1 = ndirs[f * 3 + 1], d2 = ndirs[f * 3 + 2];
        float m = -INFINITY;
#pragma unroll
        for (int k = 0; k < KNNK; k++) {
            float th = fmaxf(sdx[kb + k] * d0 + sdy[kb + k] * d1 + sdz[kb + k] * d2, 0.f);
            float fs = fo[(size_t)sj[kb + k] * C + OC + f];
            m = fmaxf(m, th * fs);
        }
        float val = forow[f] + m;
        if (relu_out) val = fmaxf(val, 0.f);
        out[(size_t)p * OC + f] = val;
    }
}

// ======================= gather + max (float4) =======================
__global__ void gather_max4_kernel(const float* __restrict__ fm, const int* __restrict__ nb,
                                   float* __restrict__ out, int N, int F) {
    int F4 = F / 4;
    int idx = blockIdx.x * blockDim.x + threadIdx.x;
    int tot = BATCH * N * F4;
    if (idx >= tot) return;
    int f4 = idx % F4; int p = idx / F4; int b = p / N;
    const int* nbp = nb + (size_t)p * KNNK;
    float4 m = make_float4(-INFINITY, -INFINITY, -INFINITY, -INFINITY);
#pragma unroll
    for (int k = 0; k < KNNK; k++) {
        const float4 vv = *(const float4*)&fm[((size_t)b * N + nbp[k]) * F + f4 * 4];
        m.x = fmaxf(m.x, vv.x); m.y = fmaxf(m.y, vv.y);
        m.z = fmaxf(m.z, vv.z); m.w = fmaxf(m.w, vv.w);
    }
    *(float4*)&out[(size_t)p * F + f4 * 4] = m;
}

// ======================= gather rows (pool) =======================
__global__ void gather_rows4_kernel(const float* __restrict__ in, const int* __restrict__ pool,
                                    float* __restrict__ out, int Nin, int Nout, int F) {
    int F4 = F / 4;
    int idx = blockIdx.x * blockDim.x + threadIdx.x;
    int tot = BATCH * Nout * F4;
    if (idx >= tot) return;
    int f4 = idx % F4; int r = idx / F4; int b = r / Nout; int pp = r % Nout;
    *(float4*)&out[(size_t)r * F + f4 * 4] =
        *(const float4*)&in[((size_t)b * Nin + pool[pp]) * F + f4 * 4];
}

__global__ void gather_rows_kernel(const float* __restrict__ in, const int* __restrict__ pool,
                                   float* __restrict__ out, int Nin, int Nout, int F) {
    int idx = blockIdx.x * blockDim.x + threadIdx.x;
    int tot = BATCH * Nout * F;
    if (idx >= tot) return;
    int f = idx % F; int r = idx / F; int b = r / Nout; int pp = r % Nout;
    out[idx] = in[((size_t)b * Nin + pool[pp]) * F + f];
}

// ======================= fp32 GEMM, float4 global + LDS.128 (M%64==0, N%64==0, K%16==0) ===
__global__ void gemm_kernel(const float* __restrict__ A, const float* __restrict__ B,
                            const float* __restrict__ bias, float* __restrict__ C,
                            int M, int K, int N) {
    __shared__ float As[16][68];
    __shared__ float Bs[16][68];
    int row0 = blockIdx.y * 64, col0 = blockIdx.x * 64;
    int tid = threadIdx.x;
    int tx = tid % 16, ty = tid / 16;
    float acc[4][4] = {};
    int ar = tid >> 2, ac4 = (tid & 3) * 4;
    int br = tid >> 4, bc4 = (tid & 15) * 4;
    for (int k0 = 0; k0 < K; k0 += 16) {
        float4 av = *(const float4*)&A[(size_t)(row0 + ar) * K + k0 + ac4];
        As[ac4][ar] = av.x; As[ac4 + 1][ar] = av.y; As[ac4 + 2][ar] = av.z; As[ac4 + 3][ar] = av.w;
        *(float4*)&Bs[br][bc4] = *(const float4*)&B[(size_t)(k0 + br) * N + col0 + bc4];
        __syncthreads();
#pragma unroll
        for (int kk = 0; kk < 16; kk++) {
            float4 a = *(const float4*)&As[kk][ty * 4];
            float4 bb = *(const float4*)&Bs[kk][tx * 4];
            acc[0][0] = fmaf(a.x, bb.x, acc[0][0]); acc[0][1] = fmaf(a.x, bb.y, acc[0][1]);
            acc[0][2] = fmaf(a.x, bb.z, acc[0][2]); acc[0][3] = fmaf(a.x, bb.w, acc[0][3]);
            acc[1][0] = fmaf(a.y, bb.x, acc[1][0]); acc[1][1] = fmaf(a.y, bb.y, acc[1][1]);
            acc[1][2] = fmaf(a.y, bb.z, acc[1][2]); acc[1][3] = fmaf(a.y, bb.w, acc[1][3]);
            acc[2][0] = fmaf(a.z, bb.x, acc[2][0]); acc[2][1] = fmaf(a.z, bb.y, acc[2][1]);
            acc[2][2] = fmaf(a.z, bb.z, acc[2][2]); acc[2][3] = fmaf(a.z, bb.w, acc[2][3]);
            acc[3][0] = fmaf(a.w, bb.x, acc[3][0]); acc[3][1] = fmaf(a.w, bb.y, acc[3][1]);
            acc[3][2] = fmaf(a.w, bb.z, acc[3][2]); acc[3][3] = fmaf(a.w, bb.w, acc[3][3]);
        }
        __syncthreads();
    }
    float4 bz = make_float4(0.f, 0.f, 0.f, 0.f);
    if (bias) bz = *(const float4*)&bias[col0 + tx * 4];
#pragma unroll
    for (int i = 0; i < 4; i++) {
        float4 r = make_float4(acc[i][0] + bz.x, acc[i][1] + bz.y, acc[i][2] + bz.z, acc[i][3] + bz.w);
        *(float4*)&C[(size_t)(row0 + ty * 4 + i) * N + col0 + tx * 4] = r;
    }
}

// ======================= Kahan GEMM (NetVLAD cluster) =======================
__global__ void gemm_kahan_kernel(const float* __restrict__ A, const float* __restrict__ B,
                                  float* __restrict__ C, int M, int K, int N) {
    __shared__ float As[16][68];
    __shared__ float Bs[16][68];
    int row0 = blockIdx.y * 64, col0 = blockIdx.x * 64;
    int tid = threadIdx.x;
    int tx = tid % 16, ty = tid / 16;
    float acc[4][4] = {}; float cmp[4][4] = {};
    int ar = tid >> 2, ac4 = (tid & 3) * 4;
    int br = tid >> 4, bc4 = (tid & 15) * 4;
    for (int k0 = 0; k0 < K; k0 += 16) {
        float4 av = *(const float4*)&A[(size_t)(row0 + ar) * K + k0 + ac4];
        As[ac4][ar] = av.x; As[ac4 + 1][ar] = av.y; As[ac4 + 2][ar] = av.z; As[ac4 + 3][ar] = av.w;
        *(float4*)&Bs[br][bc4] = *(const float4*)&B[(size_t)(k0 + br) * N + col0 + bc4];
        __syncthreads();
#pragma unroll
        for (int kk = 0; kk < 16; kk++) {
            float a[4], bb[4];
            float4 a4 = *(const float4*)&As[kk][ty * 4];
            float4 b4 = *(const float4*)&Bs[kk][tx * 4];
            a[0] = a4.x; a[1] = a4.y; a[2] = a4.z; a[3] = a4.w;
            bb[0] = b4.x; bb[1] = b4.y; bb[2] = b4.z; bb[3] = b4.w;
#pragma unroll
            for (int i = 0; i < 4; i++)
#pragma unroll
                for (int j = 0; j < 4; j++) kadd(acc[i][j], cmp[i][j], __fmul_rn(a[i], bb[j]));
        }
        __syncthreads();
    }
#pragma unroll
    for (int i = 0; i < 4; i++)
#pragma unroll
        for (int j = 0; j < 4; j++)
            C[(size_t)(row0 + ty * 4 + i) * N + col0 + tx * 4 + j] = acc[i][j];
}

// ======================= GeM pooling (float4, fast pow) =======================
__device__ __forceinline__ float fast_pow(float x, float p) {
    return exp2f(p * log2f(x));
}
__global__ void gem_kernel(const float* __restrict__ fm4, const float* __restrict__ gem_p,
                           float* __restrict__ y) {
    int idx = blockIdx.x * blockDim.x + threadIdx.x;   // over BATCH*1024/4
    if (idx >= BATCH * 256) return;
    int b = idx / 256, c4 = (idx % 256) * 4;
    float p = gem_p[0];
    float s[4] = {}; float sc[4] = {};
    for (int n = 0; n < N3; n++) {
        float4 f = *(const float4*)&fm4[((size_t)b * N3 + n) * 1024 + c4];
        kadd(s[0], sc[0], fast_pow(fmaxf(f.x, 1e-6f), p));
        kadd(s[1], sc[1], fast_pow(fmaxf(f.y, 1e-6f), p));
        kadd(s[2], sc[2], fast_pow(fmaxf(f.z, 1e-6f), p));
        kadd(s[3], sc[3], fast_pow(fmaxf(f.w, 1e-6f), p));
    }
    float4 r;
    r.x = fast_pow(s[0] / (float)N3, 1.f / p);
    r.y = fast_pow(s[1] / (float)N3, 1.f / p);
    r.z = fast_pow(s[2] / (float)N3, 1.f / p);
    r.w = fast_pow(s[3] / (float)N3, 1.f / p);
    *(float4*)&y[b * 1024 + c4] = r;
}

// ======================= NetVLAD =======================
__global__ void bn1_stats_kernel(const float* __restrict__ act, float* __restrict__ mean,
                                 float* __restrict__ var, int rows) {
    int k = blockIdx.x;
    __shared__ double sd[256];
    float a = 0.f, ac = 0.f;
    for (int r = threadIdx.x; r < rows; r += 256) kadd(a, ac, act[(size_t)r * 64 + k]);
    sd[threadIdx.x] = (double)a; __syncthreads();
    for (int s = 128; s > 0; s >>= 1) {
        if (threadIdx.x < s) sd[threadIdx.x] += sd[threadIdx.x + s];
        __syncthreads();
    }
    float m = (float)(sd[0] / rows);
    __syncthreads();
    float q = 0.f, qc = 0.f;
    for (int r = threadIdx.x; r < rows; r += 256) {
        float d = __fadd_rn(act[(size_t)r * 64 + k], -m);
        kadd(q, qc, __fmul_rn(d, d));
    }
    sd[threadIdx.x] = (double)q; __syncthreads();
    for (int s = 128; s > 0; s >>= 1) {
        if (threadIdx.x < s) sd[threadIdx.x] += sd[threadIdx.x + s];
        __syncthreads();
    }
    if (threadIdx.x == 0) { mean[k] = m; var[k] = (float)(sd[0] / rows); }
}

__global__ void bn_softmax_kernel(float* __restrict__ act, const float* __restrict__ mean,
                                  const float* __restrict__ var, const float* __restrict__ g,
                                  const float* __restrict__ bb) {
    int r = blockIdx.x; int k = threadIdx.x;
    __shared__ float sv[64];
    float v = (act[(size_t)r * 64 + k] - mean[k]) * rsqrtf(var[k] + 1e-5f) * g[k] + bb[k];
    sv[k] = v; __syncthreads();
    float mx = -INFINITY;
    for (int t = 0; t < 64; t++) mx = fmaxf(mx, sv[t]);
    float e = expf(v - mx);
    __syncthreads(); sv[k] = e; __syncthreads();
    float s = 0.f, sc = 0.f;
    for (int t = 0; t < 64; t++) kadd(s, sc, sv[t]);
    act[(size_t)r * 64 + k] = e / s;
}

__global__ void asum_kernel(const float* __restrict__ act, float* __restrict__ asum) {
    int t = blockIdx.x * blockDim.x + threadIdx.x;
    if (t >= BATCH * 64) return;
    int b = t / 64, k = t % 64;
    float s = 0.f, sc = 0.f;
    for (int m = 0; m < N3; m++) kadd(s, sc, act[((size_t)b * N3 + m) * 64 + k]);
    asum[t] = s;
}

// blockDim 256 = 4 f-slots x 64 k
__global__ void vlad_kernel(const float* __restrict__ act, const float* __restrict__ xv,
                            const float* __restrict__ asum, const float* __restrict__ cw2,
                            float* __restrict__ vlad) {
    int b = blockIdx.y;
    int k = threadIdx.x % 64;
    int f = blockIdx.x * 4 + threadIdx.x / 64;
    float s = 0.f, sc = 0.f;
    for (int m = 0; m < N3; m++) {
        kadd(s, sc, __fmul_rn(act[((size_t)b * N3 + m) * 64 + k], xv[((size_t)b * N3 + m) * 1024 + f]));
    }
    s = __fadd_rn(s, -__fmul_rn(asum[b * 64 + k], cw2[(size_t)f * 64 + k]));
    vlad[((size_t)b * 1024 + f) * 64 + k] = s;
}

__global__ void colnorm_kernel(const float* __restrict__ vlad, float* __restrict__ cn) {
    int b = blockIdx.x; int tid = threadIdx.x;
    int k = tid % 64, grp = tid / 64;  // 16 groups
    float s = 0.f, sc = 0.f;
    for (int f = grp; f < 1024; f += 16) {
        float v = vlad[((size_t)b * 1024 + f) * 64 + k];
        kadd(s, sc, __fmul_rn(v, v));
    }
    __shared__ double sm[1024];
    sm[tid] = (double)s; __syncthreads();
    if (grp == 0) {
        double t = 0.0;
        for (int g2 = 0; g2 < 16; g2++) t += sm[g2 * 64 + k];
        cn[b * 64 + k] = (float)t;
    }
}

__global__ void tn_kernel(const float* __restrict__ cn, float* __restrict__ tn) {
    int b = threadIdx.x;
    if (b >= BATCH) return;
    double s = 0.0;
    for (int k = 0; k < 64; k++) {
        float c = cn[b * 64 + k];
        float d = fmaxf(sqrtf(c), 1e-12f);
        s += (double)(c / (d * d));
    }
    tn[b] = (float)s;
}

__global__ void vnorm_kernel(float* __restrict__ vlad, const float* __restrict__ cn,
                             const float* __restrict__ tn) {
    int idx = blockIdx.x * blockDim.x + threadIdx.x;
    if (idx >= BATCH * 1024 * 64) return;
    int k = idx % 64; int b = idx / (1024 * 64);
    float d1 = fmaxf(sqrtf(cn[b * 64 + k]), 1e-12f);
    float d2 = fmaxf(sqrtf(tn[b]), 1e-12f);
    vlad[idx] = vlad[idx] / d1 / d2;
}

#define SKC 1024
__global__ void skinny8_kernel(const float* __restrict__ A, const float* __restrict__ W,
                               float* __restrict__ part, int K, int N) {
    int j = blockIdx.x * 256 + threadIdx.x;
    int k0 = blockIdx.y * SKC;
    int len = min(SKC, K - k0);
    __shared__ float xs[BATCH * SKC];
    for (int t = threadIdx.x; t < BATCH * len; t += 256) {
        int bb = t / len; int ii = t % len;
        xs[bb * len + ii] = A[(size_t)bb * K + k0 + ii];
    }
    __syncthreads();
    if (j < N) {
        float acc[BATCH] = {}; float cmp[BATCH] = {};
        for (int i = 0; i < len; i++) {
            float w = W[(size_t)(k0 + i) * N + j];
#pragma unroll
            for (int bb = 0; bb < BATCH; bb++) kadd(acc[bb], cmp[bb], __fmul_rn(xs[bb * len + i], w));
        }
#pragma unroll
        for (int bb = 0; bb < BATCH; bb++) {
            part[(size_t)blockIdx.y * BATCH * N + bb * N + j] = acc[bb];
        }
    }
}

__global__ void reduce_chunks_kernel(const float* __restrict__ part, float* __restrict__ out,
                                     int nchunks, int tot) {
    int idx = blockIdx.x * blockDim.x + threadIdx.x;
    if (idx >= tot) return;
    float s = 0.f, sc = 0.f;
    for (int c = 0; c < nchunks; c++) kadd(s, sc, part[(size_t)c * tot + idx]);
    out[idx] = s;
}

__global__ void bn8_kernel(const float* __restrict__ in, const float* __restrict__ g,
                           const float* __restrict__ bb, float* __restrict__ out, int N) {
    int j = blockIdx.x * blockDim.x + threadIdx.x;
    if (j >= N) return;
    double m = 0.0;
    for (int b = 0; b < BATCH; b++) m += (double)in[b * N + j];
    m /= BATCH;
    double q = 0.0;
    for (int b = 0; b < BATCH; b++) { double d = (double)in[b * N + j] - m; q += d * d; }
    q /= BATCH;
    float mf = (float)m;
    float inv = rsqrtf((float)q + 1e-5f);
    for (int b = 0; b < BATCH; b++) out[b * N + j] = (in[b * N + j] - mf) * inv * g[j] + bb[j];
}

__global__ void gate_final_kernel(const float* __restrict__ vbn, const float* __restrict__ gpre,
                                  const float* __restrict__ gg, const float* __restrict__ gb,
                                  float* __restrict__ desc) {
    int j = blockIdx.x * blockDim.x + threadIdx.x;
    if (j >= 1024) return;
    double m = 0.0;
    for (int b = 0; b < BATCH; b++) m += (double)gpre[b * 1024 + j];
    m /= BATCH;
    double q = 0.0;
    for (int b = 0; b < BATCH; b++) { double d = (double)gpre[b * 1024 + j] - m; q += d * d; }
    q /= BATCH;
    float mf = (float)m;
    float inv = rsqrtf((float)q + 1e-5f);
    for (int b = 0; b < BATCH; b++) {
        float z = (gpre[b * 1024 + j] - mf) * inv * gg[j] + gb[j];
        float s = 1.f / (1.f + expf(-z));
        desc[b * 1024 + j] = vbn[b * 1024 + j] * s;
    }
}

// ======================= host: numpy-compatible MT19937 pools =======================
struct MTState { uint32_t mt[624]; int idx; };

static void mt_seed(MTState& s, uint32_t seed) {
    for (int p = 0; p < 624; p++) {
        s.mt[p] = seed;
        seed = 1812433253u * (seed ^ (seed >> 30)) + (uint32_t)p + 1u;
    }
    s.idx = 624;
}
static uint32_t mt_next(MTState& s) {
    if (s.idx >= 624) {
        for (int i = 0; i < 624; i++) {
            uint32_t y = (s.mt[i] & 0x80000000u) | (s.mt[(i + 1) % 624] & 0x7fffffffu);
            uint32_t v = s.mt[(i + 397) % 624] ^ (y >> 1);
            if (y & 1u) v ^= 0x9908b0dfu;
            s.mt[i] = v;
        }
        s.idx = 0;
    }
    uint32_t y = s.mt[s.idx++];
    y ^= y >> 11;
    y ^= (y << 7) & 0x9d2c5680u;
    y ^= (y << 15) & 0xefc60000u;
    y ^= y >> 18;
    return y;
}
static uint32_t rk_interval(MTState& s, uint32_t mx) {
    if (mx == 0) return 0;
    uint32_t mask = mx;
    mask |= mask >> 1; mask |= mask >> 2; mask |= mask >> 4;
    mask |= mask >> 8; mask |= mask >> 16;
    uint32_t v;
    while ((v = (mt_next(s) & mask)) > mx) {}
    return v;
}
static void np_permutation(uint32_t seed, int n, int* out) {
    for (int i = 0; i < n; i++) out[i] = i;
    MTState s; mt_seed(s, seed);
    for (int i = n - 1; i >= 1; i--) {
        uint32_t j = rk_interval(s, (uint32_t)i);
        int t = out[i]; out[i] = out[(int)j]; out[(int)j] = t;
    }
}

// ======================= launch =======================
extern "C" void kernel_launch(void* const* d_in, const int* in_sizes, int n_in,
                              void* d_out, int out_size) {
    const float* x         = (const float*)d_in[0];
    const float* dir0      = (const float*)d_in[1];
    const float* W1        = (const float*)d_in[2];
    const float* b1        = (const float*)d_in[3];
    const float* dir1      = (const float*)d_in[4];
    const float* W2        = (const float*)d_in[5];
    const float* b2        = (const float*)d_in[6];
    const float* dir2      = (const float*)d_in[7];
    const float* W3        = (const float*)d_in[8];
    const float* b3        = (const float*)d_in[9];
    const float* dir3      = (const float*)d_in[10];
    const float* W4        = (const float*)d_in[11];
    const float* b4        = (const float*)d_in[12];
    const float* dir4      = (const float*)d_in[13];
    const float* gem_p     = (const float*)d_in[14];
    const float* cluster_w = (const float*)d_in[15];
    const float* cluster_w2= (const float*)d_in[16];
    const float* hidden_w  = (const float*)d_in[17];
    const float* bn1_g     = (const float*)d_in[18];
    const float* bn1_b     = (const float*)d_in[19];
    const float* bn2_g     = (const float*)d_in[20];
    const float* bn2_b     = (const float*)d_in[21];
    const float* gating_w  = (const float*)d_in[22];
    const float* gbn_g     = (const float*)d_in[23];
    const float* gbn_b     = (const float*)d_in[24];
    float* out = (float*)d_out;

    float *fo, *fa, *fb, *ndirs, *v2, *v3, *act, *bnm, *bnv, *asum, *vlad, *cn, *tn, *part, *hidden, *vbn, *gpre;
    int *nb, *pool1, *pool2;
    cudaGetSymbolAddress((void**)&fo, g_fo);
    cudaGetSymbolAddress((void**)&fa, g_fa);
    cudaGetSymbolAddress((void**)&fb, g_fb);
    cudaGetSymbolAddress((void**)&nb, g_nb);
    cudaGetSymbolAddress((void**)&ndirs, g_ndirs);
    cudaGetSymbolAddress((void**)&pool1, g_pool1);
    cudaGetSymbolAddress((void**)&pool2, g_pool2);
    cudaGetSymbolAddress((void**)&v2, g_v2);
    cudaGetSymbolAddress((void**)&v3, g_v3);
    cudaGetSymbolAddress((void**)&act, g_act);
    cudaGetSymbolAddress((void**)&bnm, g_bnm);
    cudaGetSymbolAddress((void**)&bnv, g_bnv);
    cudaGetSymbolAddress((void**)&asum, g_asum);
    cudaGetSymbolAddress((void**)&vlad, g_vlad);
    cudaGetSymbolAddress((void**)&cn, g_cn);
    cudaGetSymbolAddress((void**)&tn, g_tn);
    cudaGetSymbolAddress((void**)&part, g_part);
    cudaGetSymbolAddress((void**)&hidden, g_hidden);
    cudaGetSymbolAddress((void**)&vbn, g_vbn);
    cudaGetSymbolAddress((void**)&gpre, g_gpre);

    static PoolParams pp;
    {
        static int perm1[N1];
        static int perm2[N2];
        np_permutation(1u, N1, perm1);
        np_permutation(2u, N2, perm2);
        for (int i = 0; i < 1024; i++) pp.p1[i] = perm1[i];
        for (int i = 0; i < 256;  i++) pp.p2[i] = perm2[i];
    }
    set_pools_kernel<<<1, 256>>>(pp);
    norm_dirs_all_kernel<<<6, 256>>>(dir0, dir1, dir2, dir3, dir4);

    const float* nd0 = ndirs;
    const float* nd1 = ndirs + 32 * 3;
    const float* nd2 = ndirs + 96 * 3;
    const float* nd3 = ndirs + 224 * 3;
    const float* nd4 = ndirs + 480 * 3;

    // ================= stage 1 (4096 pts) =================
    knn_kernel<<<dim3(N1 / 128, BATCH), 128>>>(x, N1, nb);
    conv_surface_kernel<<<BATCH * N1 / 8, 256>>>(x, nb, nd0, fa, N1, 32, 8);

    gemm_kernel<<<dim3(2, BATCH * N1 / 64), 256>>>(fa, W1, b1, fo, BATCH * N1, 32, 128);
    conv_act_kernel<<<BATCH * N1 / 4, 256>>>(x, nb, nd1, fo, fb, N1, 64, 4, 1);

    gather_max4_kernel<<<(BATCH * N1 * 16 + 255) / 256, 256>>>(fb, nb, fa, N1, 64);
    gather_rows4_kernel<<<(BATCH * N2 * 16 + 255) / 256, 256>>>(fa, pool1, fb, N1, N2, 64);
    gather_rows_kernel<<<(BATCH * N2 * 3 + 255) / 256, 256>>>(x, pool1, v2, N1, N2, 3);

    // ================= stage 2 (1024 pts) =================
    knn_kernel<<<dim3(N2 / 128, BATCH), 128>>>(v2, N2, nb);

    gemm_kernel<<<dim3(4, BATCH * N2 / 64), 256>>>(fb, W2, b2, fo, BATCH * N2, 64, 256);
    conv_act_kernel<<<BATCH * N2 / 2, 256>>>(v2, nb, nd2, fo, fa, N2, 128, 2, 1);

    gemm_kernel<<<dim3(8, BATCH * N2 / 64), 256>>>(fa, W3, b3, fo, BATCH * N2, 128, 512);
    conv_act_kernel<<<BATCH * N2, 256>>>(v2, nb, nd3, fo, fb, N2, 256, 1, 1);

    gather_max4_kernel<<<(BATCH * N2 * 64 + 255) / 256, 256>>>(fb, nb, fa, N2, 256);
    gather_rows4_kernel<<<(BATCH * N3 * 64 + 255) / 256, 256>>>(fa, pool2, fb, N2, N3, 256);
    gather_rows_kernel<<<(BATCH * N3 * 3 + 255) / 256, 256>>>(v2, pool2, v3, N2, N3, 3);

    // ================= stage 3 (256 pts) =================
    knn_kernel<<<dim3(N3 / 128, BATCH), 128>>>(v3, N3, nb);

    gemm_kernel<<<dim3(32, BATCH * N3 / 64), 256>>>(fb, W4, b4, fo, BATCH * N3, 256, 2048);
    conv_act_kernel<<<BATCH * N3, 256>>>(v3, nb, nd4, fo, fa, N3, 1024, 1, 0);

    // ---- GeM -> y ----
    gem_kernel<<<(BATCH * 256 + 255) / 256, 256>>>(fa, gem_p, out);

    // ================= NetVLAD =================
    gemm_kahan_kernel<<<dim3(1, BATCH * N3 / 64), 256>>>(fa, cluster_w, act, BATCH * N3, 1024, 64);
    bn1_stats_kernel<<<64, 256>>>(act, bnm, bnv, BATCH * N3);
    bn_softmax_kernel<<<BATCH * N3, 64>>>(act, bnm, bnv, bn1_g, bn1_b);
    asum_kernel<<<2, 256>>>(act, asum);
    vlad_kernel<<<dim3(256, BATCH), 256>>>(act, fa, asum, cluster_w2, vlad);
    colnorm_kernel<<<BATCH, 1024>>>(vlad, cn);
    tn_kernel<<<1, 32>>>(cn, tn);
    vnorm_kernel<<<(BATCH * 1024 * 64 + 255) / 256, 256>>>(vlad, cn, tn);

    skinny8_kernel<<<dim3(4, 64), 256>>>(vlad, hidden_w, part, 65536, 1024);
    reduce_chunks_kernel<<<(BATCH * 1024 + 255) / 256, 256>>>(part, hidden, 64, BATCH * 1024);
    bn8_kernel<<<4, 256>>>(hidden, bn2_g, bn2_b, vbn, 1024);

    skinny8_kernel<<<dim3(4, 1), 256>>>(vbn, gating_w, part, 1024, 1024);
    reduce_chunks_kernel<<<(BATCH * 1024 + 255) / 256, 256>>>(part, gpre, 1, BATCH * 1024);
    gate_final_kernel<<<4, 256>>>(vbn, gpre, gbn_g, gbn_b, out + BATCH * 1024);
}

// round 4
// speedup vs baseline: 2.2283x; 1.2639x over previous
#include <cuda_runtime.h>
#include <math.h>
#include <stdint.h>

#define BATCH 8
#define KNNK 20
#define N1 4096
#define N2 1024
#define N3 256

// ======================= device scratch =======================
__device__ float g_fo[BATCH * 4096 * 128];
__device__ float g_fa[BATCH * 4096 * 64];
__device__ float g_fb[BATCH * 4096 * 64];
__device__ int   g_nb[BATCH * 4096 * KNNK];
__device__ float g_ndirs[1504 * 3];
__device__ int   g_pool1[1024];
__device__ int   g_pool2[256];
__device__ float g_v2[BATCH * 1024 * 3];
__device__ float g_v3[BATCH * 256 * 3];
__device__ float g_act[BATCH * 256 * 64];
__device__ float g_bnm[64];
__device__ float g_bnv[64];
__device__ float g_asum[BATCH * 64];
__device__ float g_vlad[BATCH * 1024 * 64];
__device__ float g_cn[BATCH * 64];
__device__ float g_tn[BATCH];
__device__ float g_part[64 * BATCH * 1024];
__device__ float g_hidden[BATCH * 1024];
__device__ float g_vbn[BATCH * 1024];
__device__ float g_gpre[BATCH * 1024];

__device__ __forceinline__ void kadd(float& s, float& c, float v) {
    float y = __fadd_rn(v, -c);
    float t = __fadd_rn(s, y);
    c = __fadd_rn(__fadd_rn(t, -s), -y);
    s = t;
}

// ======================= pools =======================
struct PoolParams { int p1[1024]; int p2[256]; };

__global__ void set_pools_kernel(PoolParams pp) {
    for (int i = threadIdx.x; i < 1024; i += blockDim.x) g_pool1[i] = pp.p1[i];
    for (int i = threadIdx.x; i < 256;  i += blockDim.x) g_pool2[i] = pp.p2[i];
}

// ======================= direction normalizations (all 5 upfront) =======================
__global__ void norm_dirs_all_kernel(const float* __restrict__ d0, const float* __restrict__ d1,
                                     const float* __restrict__ d2, const float* __restrict__ d3,
                                     const float* __restrict__ d4) {
    int t = blockIdx.x * blockDim.x + threadIdx.x;
    const float* src; int F, off, f;
    if      (t < 32)   { src = d0; F = 32;   off = 0;   f = t; }
    else if (t < 96)   { src = d1; F = 64;   off = 32;  f = t - 32; }
    else if (t < 224)  { src = d2; F = 128;  off = 96;  f = t - 96; }
    else if (t < 480)  { src = d3; F = 256;  off = 224; f = t - 224; }
    else if (t < 1504) { src = d4; F = 1024; off = 480; f = t - 480; }
    else return;
    float a = src[f], b = src[F + f], c = src[2 * F + f];
    float n = fmaxf(sqrtf(a * a + b * b + c * c), 1e-12f);
    g_ndirs[(off + f) * 3]     = a / n;
    g_ndirs[(off + f) * 3 + 1] = b / n;
    g_ndirs[(off + f) * 3 + 2] = c / n;
}

// ======================= KNN =======================
// strict d<worst keeps earliest index on ties (stored entries always have lower j),
// which matches lax.top_k's lower-index-wins set exactly.
#define KNN_TILE 128
__global__ void knn_kernel(const float* __restrict__ v, int N, int* __restrict__ nb) {
    int b = blockIdx.y;
    int i = blockIdx.x * blockDim.x + threadIdx.x;
    const float* vb = v + (size_t)b * N * 3;
    float xi = vb[i * 3], yi = vb[i * 3 + 1], zi = vb[i * 3 + 2];
    float sqi = __fadd_rn(__fadd_rn(__fmul_rn(xi, xi), __fmul_rn(yi, yi)), __fmul_rn(zi, zi));

    float bd[KNNK]; int bi_[KNNK];
#pragma unroll
    for (int t = 0; t < KNNK; t++) { bd[t] = INFINITY; bi_[t] = 0x7fffffff; }
    float worst_d = INFINITY; int wslot = 0;

    __shared__ float4 sp[KNN_TILE];
    for (int base = 0; base < N; base += KNN_TILE) {
        {
            int t = threadIdx.x;
            float X = vb[(base + t) * 3], Y = vb[(base + t) * 3 + 1], Z = vb[(base + t) * 3 + 2];
            float S = __fadd_rn(__fadd_rn(__fmul_rn(X, X), __fmul_rn(Y, Y)), __fmul_rn(Z, Z));
            sp[t] = make_float4(X, Y, Z, S);
        }
        __syncthreads();
        for (int t = 0; t < KNN_TILE; t++) {
            int j = base + t;
            float4 q = sp[t];
            float dot = fmaf(zi, q.z, fmaf(yi, q.y, __fmul_rn(xi, q.x)));
            float d = __fadd_rn(__fadd_rn(sqi, q.w), -__fmul_rn(2.f, dot));
            if (j == i) continue;
            if (d < worst_d) {
#pragma unroll
                for (int s = 0; s < KNNK; s++) if (s == wslot) { bd[s] = d; bi_[s] = j; }
                worst_d = bd[0]; wslot = 0;
#pragma unroll
                for (int s = 1; s < KNNK; s++) {
                    if (bd[s] > worst_d) { worst_d = bd[s]; wslot = s; }
                }
            }
        }
        __syncthreads();
    }
#pragma unroll
    for (int t = 0; t < KNNK; t++) nb[((size_t)b * N + i) * KNNK + t] = bi_[t];
}

// ======================= conv_surface =======================
__global__ void conv_surface_kernel(const float* __restrict__ v, const int* __restrict__ nb,
                                    const float* __restrict__ ndirs, float* __restrict__ fm,
                                    int N, int OC, int G) {
    __shared__ float sdx[160], sdy[160], sdz[160];
    int p0 = blockIdx.x * G;
    int t = threadIdx.x;
    if (t < G * KNNK) {
        int g = t / KNNK, k = t % KNNK;
        int p = p0 + g; int b = p / N; int n = p % N;
        const float* vb = v + (size_t)b * N * 3;
        int j = nb[(size_t)p * KNNK + k];
        float dx = vb[j * 3] - vb[n * 3];
        float dy = vb[j * 3 + 1] - vb[n * 3 + 1];
        float dz = vb[j * 3 + 2] - vb[n * 3 + 2];
        float nm = fmaxf(sqrtf(dx * dx + dy * dy + dz * dz), 1e-12f);
        sdx[t] = dx / nm; sdy[t] = dy / nm; sdz[t] = dz / nm;
    }
    __syncthreads();
    int OCc = 256 / G;
    int g = t / OCc, f = t % OCc;
    int p = p0 + g;
    float d0 = ndirs[f * 3], d1 = ndirs[f * 3 + 1], d2 = ndirs[f * 3 + 2];
    float m = 0.f;
    int kb = g * KNNK;
#pragma unroll
    for (int k = 0; k < KNNK; k++) {
        float th = fmaxf(sdx[kb + k] * d0 + sdy[kb + k] * d1 + sdz[kb + k] * d2, 0.f);
        m = fmaxf(m, th);
    }
    fm[(size_t)p * OC + f] = m;
}

// ======================= conv_layer activation =======================
__global__ void conv_act_kernel(const float* __restrict__ v, const int* __restrict__ nb,
                                const float* __restrict__ ndirs, const float* __restrict__ fo,
                                float* __restrict__ out, int N, int OC, int G, int relu_out) {
    int C = 2 * OC;
    __shared__ float sdx[160], sdy[160], sdz[160];
    __shared__ int sj[160];
    int p0 = blockIdx.x * G;
    int t = threadIdx.x;
    if (t < G * KNNK) {
        int g = t / KNNK, k = t % KNNK;
        int p = p0 + g; int b = p / N; int n = p % N;
        const float* vb = v + (size_t)b * N * 3;
        int j = nb[(size_t)p * KNNK + k];
        sj[t] = b * N + j;
        float dx = vb[j * 3] - vb[n * 3];
        float dy = vb[j * 3 + 1] - vb[n * 3 + 1];
        float dz = vb[j * 3 + 2] - vb[n * 3 + 2];
        float nm = fmaxf(sqrtf(dx * dx + dy * dy + dz * dz), 1e-12f);
        sdx[t] = dx / nm; sdy[t] = dy / nm; sdz[t] = dz / nm;
    }
    __syncthreads();
    int OCc = 256 / G;
    int g = t / OCc, fb = t % OCc;
    int p = p0 + g;
    int kb = g * KNNK;
    const float* forow = fo + (size_t)p * C;
    for (int f = fb; f < OC; f += OCc) {
        float d0 = ndirs[f * 3], d1 = ndirs[f * 3 + 1], d2 = ndirs[f * 3 + 2];
        float m = -INFINITY;
#pragma unroll
        for (int k = 0; k < KNNK; k++) {
            float th = fmaxf(sdx[kb + k] * d0 + sdy[kb + k] * d1 + sdz[kb + k] * d2, 0.f);
            float fs = fo[(size_t)sj[kb + k] * C + OC + f];
            m = fmaxf(m, th * fs);
        }
        float val = forow[f] + m;
        if (relu_out) val = fmaxf(val, 0.f);
        out[(size_t)p * OC + f] = val;
    }
}

// ======================= fused gather_max + pool: only pooled rows =======================
__global__ void gather_max_pool_kernel(const float* __restrict__ fm, const int* __restrict__ nb,
                                       const int* __restrict__ pool, float* __restrict__ out,
                                       int Nin, int Nout, int F) {
    int F4 = F / 4;
    int idx = blockIdx.x * blockDim.x + threadIdx.x;
    int tot = BATCH * Nout * F4;
    if (idx >= tot) return;
    int f4 = idx % F4; int r = idx / F4; int b = r / Nout; int pp = r % Nout;
    int row = pool[pp];
    const int* nbp = nb + ((size_t)b * Nin + row) * KNNK;
    float4 m = make_float4(-INFINITY, -INFINITY, -INFINITY, -INFINITY);
#pragma unroll
    for (int k = 0; k < KNNK; k++) {
        const float4 vv = *(const float4*)&fm[((size_t)b * Nin + nbp[k]) * F + f4 * 4];
        m.x = fmaxf(m.x, vv.x); m.y = fmaxf(m.y, vv.y);
        m.z = fmaxf(m.z, vv.z); m.w = fmaxf(m.w, vv.w);
    }
    *(float4*)&out[(size_t)r * F + f4 * 4] = m;
}

__global__ void gather_rows_kernel(const float* __restrict__ in, const int* __restrict__ pool,
                                   float* __restrict__ out, int Nin, int Nout, int F) {
    int idx = blockIdx.x * blockDim.x + threadIdx.x;
    int tot = BATCH * Nout * F;
    if (idx >= tot) return;
    int f = idx % F; int r = idx / F; int b = r / Nout; int pp = r % Nout;
    out[idx] = in[((size_t)b * Nin + pool[pp]) * F + f];
}

// ======================= 128x128 tile / 8x8 microtile SGEMM (M,N % 128 == 0, K % 8 == 0) ===
#define GT 132
__global__ __launch_bounds__(256, 2) void gemm128_kernel(
        const float* __restrict__ A, const float* __restrict__ B,
        const float* __restrict__ bias, float* __restrict__ C,
        int M, int K, int N) {
    __shared__ float As[8][GT];
    __shared__ float Bs[8][GT];
    int row0 = blockIdx.y * 128, col0 = blockIdx.x * 128;
    int tid = threadIdx.x;
    int tx = tid % 16, ty = tid / 16;
    int arow = tid >> 1, acol = (tid & 1) * 4;
    int brow = tid >> 5, bcol = (tid & 31) * 4;
    float4 pa = *(const float4*)&A[(size_t)(row0 + arow) * K + acol];
    float4 pb = *(const float4*)&B[(size_t)brow * N + col0 + bcol];
    float acc[8][8] = {};
    for (int k0 = 0; k0 < K; k0 += 8) {
        As[acol][arow] = pa.x; As[acol + 1][arow] = pa.y;
        As[acol + 2][arow] = pa.z; As[acol + 3][arow] = pa.w;
        *(float4*)&Bs[brow][bcol] = pb;
        __syncthreads();
        if (k0 + 8 < K) {
            pa = *(const float4*)&A[(size_t)(row0 + arow) * K + k0 + 8 + acol];
            pb = *(const float4*)&B[(size_t)(k0 + 8 + brow) * N + col0 + bcol];
        }
#pragma unroll
        for (int kk = 0; kk < 8; kk++) {
            float a[8], bb[8];
            *(float4*)&a[0] = *(const float4*)&As[kk][ty * 8];
            *(float4*)&a[4] = *(const float4*)&As[kk][ty * 8 + 4];
            *(float4*)&bb[0] = *(const float4*)&Bs[kk][tx * 8];
            *(float4*)&bb[4] = *(const float4*)&Bs[kk][tx * 8 + 4];
#pragma unroll
            for (int i = 0; i < 8; i++)
#pragma unroll
                for (int j = 0; j < 8; j++) acc[i][j] = fmaf(a[i], bb[j], acc[i][j]);
        }
        __syncthreads();
    }
    float bz[8];
    if (bias) {
        *(float4*)&bz[0] = *(const float4*)&bias[col0 + tx * 8];
        *(float4*)&bz[4] = *(const float4*)&bias[col0 + tx * 8 + 4];
    } else {
#pragma unroll
        for (int j = 0; j < 8; j++) bz[j] = 0.f;
    }
#pragma unroll
    for (int i = 0; i < 8; i++) {
        float* crow = &C[(size_t)(row0 + ty * 8 + i) * N + col0 + tx * 8];
        float4 r0 = make_float4(acc[i][0] + bz[0], acc[i][1] + bz[1], acc[i][2] + bz[2], acc[i][3] + bz[3]);
        float4 r1 = make_float4(acc[i][4] + bz[4], acc[i][5] + bz[5], acc[i][6] + bz[6], acc[i][7] + bz[7]);
        *(float4*)crow = r0;
        *(float4*)(crow + 4) = r1;
    }
}

// ======================= Kahan GEMM (NetVLAD cluster, N=64) =======================
__global__ void gemm_kahan_kernel(const float* __restrict__ A, const float* __restrict__ B,
                                  float* __restrict__ C, int M, int K, int N) {
    __shared__ float As[16][68];
    __shared__ float Bs[16][68];
    int row0 = blockIdx.y * 64, col0 = blockIdx.x * 64;
    int tid = threadIdx.x;
    int tx = tid % 16, ty = tid / 16;
    float acc[4][4] = {}; float cmp[4][4] = {};
    int ar = tid >> 2, ac4 = (tid & 3) * 4;
    int br = tid >> 4, bc4 = (tid & 15) * 4;
    for (int k0 = 0; k0 < K; k0 += 16) {
        float4 av = *(const float4*)&A[(size_t)(row0 + ar) * K + k0 + ac4];
        As[ac4][ar] = av.x; As[ac4 + 1][ar] = av.y; As[ac4 + 2][ar] = av.z; As[ac4 + 3][ar] = av.w;
        *(float4*)&Bs[br][bc4] = *(const float4*)&B[(size_t)(k0 + br) * N + col0 + bc4];
        __syncthreads();
#pragma unroll
        for (int kk = 0; kk < 16; kk++) {
            float a[4], bb[4];
            float4 a4 = *(const float4*)&As[kk][ty * 4];
            float4 b4 = *(const float4*)&Bs[kk][tx * 4];
            a[0] = a4.x; a[1] = a4.y; a[2] = a4.z; a[3] = a4.w;
            bb[0] = b4.x; bb[1] = b4.y; bb[2] = b4.z; bb[3] = b4.w;
#pragma unroll
            for (int i = 0; i < 4; i++)
#pragma unroll
                for (int j = 0; j < 4; j++) kadd(acc[i][j], cmp[i][j], __fmul_rn(a[i], bb[j]));
        }
        __syncthreads();
    }
#pragma unroll
    for (int i = 0; i < 4; i++)
#pragma unroll
        for (int j = 0; j < 4; j++)
            C[(size_t)(row0 + ty * 4 + i) * N + col0 + tx * 4 + j] = acc[i][j];
}

// ======================= GeM pooling =======================
__device__ __forceinline__ float fast_pow(float x, float p) {
    return exp2f(p * log2f(x));
}
__global__ void gem_kernel(const float* __restrict__ fm4, const float* __restrict__ gem_p,
                           float* __restrict__ y) {
    int idx = blockIdx.x * blockDim.x + threadIdx.x;
    if (idx >= BATCH * 256) return;
    int b = idx / 256, c4 = (idx % 256) * 4;
    float p = gem_p[0];
    bool p3 = (p == 3.0f);
    float s[4] = {}; float sc[4] = {};
    for (int n = 0; n < N3; n++) {
        float4 f = *(const float4*)&fm4[((size_t)b * N3 + n) * 1024 + c4];
        float fx = fmaxf(f.x, 1e-6f), fy = fmaxf(f.y, 1e-6f);
        float fz = fmaxf(f.z, 1e-6f), fw = fmaxf(f.w, 1e-6f);
        if (p3) {
            kadd(s[0], sc[0], fx * fx * fx);
            kadd(s[1], sc[1], fy * fy * fy);
            kadd(s[2], sc[2], fz * fz * fz);
            kadd(s[3], sc[3], fw * fw * fw);
        } else {
            kadd(s[0], sc[0], fast_pow(fx, p));
            kadd(s[1], sc[1], fast_pow(fy, p));
            kadd(s[2], sc[2], fast_pow(fz, p));
            kadd(s[3], sc[3], fast_pow(fw, p));
        }
    }
    float4 r;
    if (p3) {
        r.x = cbrtf(s[0] / (float)N3); r.y = cbrtf(s[1] / (float)N3);
        r.z = cbrtf(s[2] / (float)N3); r.w = cbrtf(s[3] / (float)N3);
    } else {
        float ip = 1.f / p;
        r.x = fast_pow(s[0] / (float)N3, ip); r.y = fast_pow(s[1] / (float)N3, ip);
        r.z = fast_pow(s[2] / (float)N3, ip); r.w = fast_pow(s[3] / (float)N3, ip);
    }
    *(float4*)&y[b * 1024 + c4] = r;
}

// ======================= NetVLAD =======================
__global__ void bn1_stats_kernel(const float* __restrict__ act, float* __restrict__ mean,
                                 float* __restrict__ var, int rows) {
    int k = blockIdx.x;
    __shared__ double sd[256];
    float a = 0.f, ac = 0.f;
    for (int r = threadIdx.x; r < rows; r += 256) kadd(a, ac, act[(size_t)r * 64 + k]);
    sd[threadIdx.x] = (double)a; __syncthreads();
    for (int s = 128; s > 0; s >>= 1) {
        if (threadIdx.x < s) sd[threadIdx.x] += sd[threadIdx.x + s];
        __syncthreads();
    }
    float m = (float)(sd[0] / rows);
    __syncthreads();
    float q = 0.f, qc = 0.f;
    for (int r = threadIdx.x; r < rows; r += 256) {
        float d = __fadd_rn(act[(size_t)r * 64 + k], -m);
        kadd(q, qc, __fmul_rn(d, d));
    }
    sd[threadIdx.x] = (double)q; __syncthreads();
    for (int s = 128; s > 0; s >>= 1) {
        if (threadIdx.x < s) sd[threadIdx.x] += sd[threadIdx.x + s];
        __syncthreads();
    }
    if (threadIdx.x == 0) { mean[k] = m; var[k] = (float)(sd[0] / rows); }
}

__global__ void bn_softmax_kernel(float* __restrict__ act, const float* __restrict__ mean,
                                  const float* __restrict__ var, const float* __restrict__ g,
                                  const float* __restrict__ bb) {
    int r = blockIdx.x; int k = threadIdx.x;
    __shared__ float sv[64];
    float v = (act[(size_t)r * 64 + k] - mean[k]) * rsqrtf(var[k] + 1e-5f) * g[k] + bb[k];
    sv[k] = v; __syncthreads();
    float mx = -INFINITY;
    for (int t = 0; t < 64; t++) mx = fmaxf(mx, sv[t]);
    float e = expf(v - mx);
    __syncthreads(); sv[k] = e; __syncthreads();
    float s = 0.f, sc = 0.f;
    for (int t = 0; t < 64; t++) kadd(s, sc, sv[t]);
    act[(size_t)r * 64 + k] = e / s;
}

__global__ void asum_kernel(const float* __restrict__ act, float* __restrict__ asum) {
    int t = blockIdx.x * blockDim.x + threadIdx.x;
    if (t >= BATCH * 64) return;
    int b = t / 64, k = t % 64;
    float s = 0.f, sc = 0.f;
    for (int m = 0; m < N3; m++) kadd(s, sc, act[((size_t)b * N3 + m) * 64 + k]);
    asum[t] = s;
}

__global__ void vlad_kernel(const float* __restrict__ act, const float* __restrict__ xv,
                            const float* __restrict__ asum, const float* __restrict__ cw2,
                            float* __restrict__ vlad) {
    int b = blockIdx.y;
    int k = threadIdx.x % 64;
    int f = blockIdx.x * 4 + threadIdx.x / 64;
    float s = 0.f, sc = 0.f;
    for (int m = 0; m < N3; m++) {
        kadd(s, sc, __fmul_rn(act[((size_t)b * N3 + m) * 64 + k], xv[((size_t)b * N3 + m) * 1024 + f]));
    }
    s = __fadd_rn(s, -__fmul_rn(asum[b * 64 + k], cw2[(size_t)f * 64 + k]));
    vlad[((size_t)b * 1024 + f) * 64 + k] = s;
}

__global__ void colnorm_kernel(const float* __restrict__ vlad, float* __restrict__ cn) {
    int b = blockIdx.x; int tid = threadIdx.x;
    int k = tid % 64, grp = tid / 64;
    float s = 0.f, sc = 0.f;
    for (int f = grp; f < 1024; f += 16) {
        float v = vlad[((size_t)b * 1024 + f) * 64 + k];
        kadd(s, sc, __fmul_rn(v, v));
    }
    __shared__ double sm[1024];
    sm[tid] = (double)s; __syncthreads();
    if (grp == 0) {
        double t = 0.0;
        for (int g2 = 0; g2 < 16; g2++) t += sm[g2 * 64 + k];
        cn[b * 64 + k] = (float)t;
    }
}

__global__ void tn_kernel(const float* __restrict__ cn, float* __restrict__ tn) {
    int b = threadIdx.x;
    if (b >= BATCH) return;
    double s = 0.0;
    for (int k = 0; k < 64; k++) {
        float c = cn[b * 64 + k];
        float d = fmaxf(sqrtf(c), 1e-12f);
        s += (double)(c / (d * d));
    }
    tn[b] = (float)s;
}

__global__ void vnorm_kernel(float* __restrict__ vlad, const float* __restrict__ cn,
                             const float* __restrict__ tn) {
    int idx = blockIdx.x * blockDim.x + threadIdx.x;
    if (idx >= BATCH * 1024 * 64) return;
    int k = idx % 64; int b = idx / (1024 * 64);
    float d1 = fmaxf(sqrtf(cn[b * 64 + k]), 1e-12f);
    float d2 = fmaxf(sqrtf(tn[b]), 1e-12f);
    vlad[idx] = vlad[idx] / d1 / d2;
}

#define SKC 1024
__global__ void skinny8_kernel(const float* __restrict__ A, const float* __restrict__ W,
                               float* __restrict__ part, int K, int N) {
    int j = blockIdx.x * 256 + threadIdx.x;
    int k0 = blockIdx.y * SKC;
    int len = min(SKC, K - k0);
    __shared__ float xs[BATCH * SKC];
    for (int t = threadIdx.x; t < BATCH * len; t += 256) {
        int bb = t / len; int ii = t % len;
        xs[bb * len + ii] = A[(size_t)bb * K + k0 + ii];
    }
    __syncthreads();
    if (j < N) {
        float acc[BATCH] = {}; float cmp[BATCH] = {};
        for (int i = 0; i < len; i++) {
            float w = W[(size_t)(k0 + i) * N + j];
#pragma unroll
            for (int bb = 0; bb < BATCH; bb++) kadd(acc[bb], cmp[bb], __fmul_rn(xs[bb * len + i], w));
        }
#pragma unroll
        for (int bb = 0; bb < BATCH; bb++) {
            part[(size_t)blockIdx.y * BATCH * N + bb * N + j] = acc[bb];
        }
    }
}

__global__ void reduce_chunks_kernel(const float* __restrict__ part, float* __restrict__ out,
                                     int nchunks, int tot) {
    int idx = blockIdx.x * blockDim.x + threadIdx.x;
    if (idx >= tot) return;
    float s = 0.f, sc = 0.f;
    for (int c = 0; c < nchunks; c++) kadd(s, sc, part[(size_t)c * tot + idx]);
    out[idx] = s;
}

__global__ void bn8_kernel(const float* __restrict__ in, const float* __restrict__ g,
                           const float* __restrict__ bb, float* __restrict__ out, int N) {
    int j = blockIdx.x * blockDim.x + threadIdx.x;
    if (j >= N) return;
    double m = 0.0;
    for (int b = 0; b < BATCH; b++) m += (double)in[b * N + j];
    m /= BATCH;
    double q = 0.0;
    for (int b = 0; b < BATCH; b++) { double d = (double)in[b * N + j] - m; q += d * d; }
    q /= BATCH;
    float mf = (float)m;
    float inv = rsqrtf((float)q + 1e-5f);
    for (int b = 0; b < BATCH; b++) out[b * N + j] = (in[b * N + j] - mf) * inv * g[j] + bb[j];
}

__global__ void gate_final_kernel(const float* __restrict__ vbn, const float* __restrict__ gpre,
                                  const float* __restrict__ gg, const float* __restrict__ gb,
                                  float* __restrict__ desc) {
    int j = blockIdx.x * blockDim.x + threadIdx.x;
    if (j >= 1024) return;
    double m = 0.0;
    for (int b = 0; b < BATCH; b++) m += (double)gpre[b * 1024 + j];
    m /= BATCH;
    double q = 0.0;
    for (int b = 0; b < BATCH; b++) { double d = (double)gpre[b * 1024 + j] - m; q += d * d; }
    q /= BATCH;
    float mf = (float)m;
    float inv = rsqrtf((float)q + 1e-5f);
    for (int b = 0; b < BATCH; b++) {
        float z = (gpre[b * 1024 + j] - mf) * inv * gg[j] + gb[j];
        float s = 1.f / (1.f + expf(-z));
        desc[b * 1024 + j] = vbn[b * 1024 + j] * s;
    }
}

// ======================= host: numpy-compatible MT19937 pools =======================
struct MTState { uint32_t mt[624]; int idx; };

static void mt_seed(MTState& s, uint32_t seed) {
    for (int p = 0; p < 624; p++) {
        s.mt[p] = seed;
        seed = 1812433253u * (seed ^ (seed >> 30)) + (uint32_t)p + 1u;
    }
    s.idx = 624;
}
static uint32_t mt_next(MTState& s) {
    if (s.idx >= 624) {
        for (int i = 0; i < 624; i++) {
            uint32_t y = (s.mt[i] & 0x80000000u) | (s.mt[(i + 1) % 624] & 0x7fffffffu);
            uint32_t v = s.mt[(i + 397) % 624] ^ (y >> 1);
            if (y & 1u) v ^= 0x9908b0dfu;
            s.mt[i] = v;
        }
        s.idx = 0;
    }
    uint32_t y = s.mt[s.idx++];
    y ^= y >> 11;
    y ^= (y << 7) & 0x9d2c5680u;
    y ^= (y << 15) & 0xefc60000u;
    y ^= y >> 18;
    return y;
}
static uint32_t rk_interval(MTState& s, uint32_t mx) {
    if (mx == 0) return 0;
    uint32_t mask = mx;
    mask |= mask >> 1; mask |= mask >> 2; mask |= mask >> 4;
    mask |= mask >> 8; mask |= mask >> 16;
    uint32_t v;
    while ((v = (mt_next(s) & mask)) > mx) {}
    return v;
}
static void np_permutation(uint32_t seed, int n, int* out) {
    for (int i = 0; i < n; i++) out[i] = i;
    MTState s; mt_seed(s, seed);
    for (int i = n - 1; i >= 1; i--) {
        uint32_t j = rk_interval(s, (uint32_t)i);
        int t = out[i]; out[i] = out[(int)j]; out[(int)j] = t;
    }
}

// ======================= launch =======================
extern "C" void kernel_launch(void* const* d_in, const int* in_sizes, int n_in,
                              void* d_out, int out_size) {
    const float* x         = (const float*)d_in[0];
    const float* dir0      = (const float*)d_in[1];
    const float* W1        = (const float*)d_in[2];
    const float* b1        = (const float*)d_in[3];
    const float* dir1      = (const float*)d_in[4];
    const float* W2        = (const float*)d_in[5];
    const float* b2        = (const float*)d_in[6];
    const float* dir2      = (const float*)d_in[7];
    const float* W3        = (const float*)d_in[8];
    const float* b3        = (const float*)d_in[9];
    const float* dir3      = (const float*)d_in[10];
    const float* W4        = (const float*)d_in[11];
    const float* b4        = (const float*)d_in[12];
    const float* dir4      = (const float*)d_in[13];
    const float* gem_p     = (const float*)d_in[14];
    const float* cluster_w = (const float*)d_in[15];
    const float* cluster_w2= (const float*)d_in[16];
    const float* hidden_w  = (const float*)d_in[17];
    const float* bn1_g     = (const float*)d_in[18];
    const float* bn1_b     = (const float*)d_in[19];
    const float* bn2_g     = (const float*)d_in[20];
    const float* bn2_b     = (const float*)d_in[21];
    const float* gating_w  = (const float*)d_in[22];
    const float* gbn_g     = (const float*)d_in[23];
    const float* gbn_b     = (const float*)d_in[24];
    float* out = (float*)d_out;

    float *fo, *fa, *fb, *ndirs, *v2, *v3, *act, *bnm, *bnv, *asum, *vlad, *cn, *tn, *part, *hidden, *vbn, *gpre;
    int *nb, *pool1, *pool2;
    cudaGetSymbolAddress((void**)&fo, g_fo);
    cudaGetSymbolAddress((void**)&fa, g_fa);
    cudaGetSymbolAddress((void**)&fb, g_fb);
    cudaGetSymbolAddress((void**)&nb, g_nb);
    cudaGetSymbolAddress((void**)&ndirs, g_ndirs);
    cudaGetSymbolAddress((void**)&pool1, g_pool1);
    cudaGetSymbolAddress((void**)&pool2, g_pool2);
    cudaGetSymbolAddress((void**)&v2, g_v2);
    cudaGetSymbolAddress((void**)&v3, g_v3);
    cudaGetSymbolAddress((void**)&act, g_act);
    cudaGetSymbolAddress((void**)&bnm, g_bnm);
    cudaGetSymbolAddress((void**)&bnv, g_bnv);
    cudaGetSymbolAddress((void**)&asum, g_asum);
    cudaGetSymbolAddress((void**)&vlad, g_vlad);
    cudaGetSymbolAddress((void**)&cn, g_cn);
    cudaGetSymbolAddress((void**)&tn, g_tn);
    cudaGetSymbolAddress((void**)&part, g_part);
    cudaGetSymbolAddress((void**)&hidden, g_hidden);
    cudaGetSymbolAddress((void**)&vbn, g_vbn);
    cudaGetSymbolAddress((void**)&gpre, g_gpre);

    static PoolParams pp;
    {
        static int perm1[N1];
        static int perm2[N2];
        np_permutation(1u, N1, perm1);
        np_permutation(2u, N2, perm2);
        for (int i = 0; i < 1024; i++) pp.p1[i] = perm1[i];
        for (int i = 0; i < 256;  i++) pp.p2[i] = perm2[i];
    }
    set_pools_kernel<<<1, 256>>>(pp);
    norm_dirs_all_kernel<<<6, 256>>>(dir0, dir1, dir2, dir3, dir4);

    const float* nd0 = ndirs;
    const float* nd1 = ndirs + 32 * 3;
    const float* nd2 = ndirs + 96 * 3;
    const float* nd3 = ndirs + 224 * 3;
    const float* nd4 = ndirs + 480 * 3;

    // ================= stage 1 (4096 pts) =================
    knn_kernel<<<dim3(N1 / 128, BATCH), 128>>>(x, N1, nb);
    conv_surface_kernel<<<BATCH * N1 / 8, 256>>>(x, nb, nd0, fa, N1, 32, 8);

    gemm128_kernel<<<dim3(1, BATCH * N1 / 128), 256>>>(fa, W1, b1, fo, BATCH * N1, 32, 128);
    conv_act_kernel<<<BATCH * N1 / 4, 256>>>(x, nb, nd1, fo, fb, N1, 64, 4, 1);

    // fused gather_max + pool1 (only 1024 pooled rows)
    gather_max_pool_kernel<<<(BATCH * N2 * 16 + 255) / 256, 256>>>(fb, nb, pool1, fa, N1, N2, 64);
    gather_rows_kernel<<<(BATCH * N2 * 3 + 255) / 256, 256>>>(x, pool1, v2, N1, N2, 3);

    // ================= stage 2 (1024 pts) =================
    knn_kernel<<<dim3(N2 / 128, BATCH), 128>>>(v2, N2, nb);

    gemm128_kernel<<<dim3(2, BATCH * N2 / 128), 256>>>(fa, W2, b2, fo, BATCH * N2, 64, 256);
    conv_act_kernel<<<BATCH * N2 / 2, 256>>>(v2, nb, nd2, fo, fb, N2, 128, 2, 1);

    gemm128_kernel<<<dim3(4, BATCH * N2 / 128), 256>>>(fb, W3, b3, fo, BATCH * N2, 128, 512);
    conv_act_kernel<<<BATCH * N2, 256>>>(v2, nb, nd3, fo, fa, N2, 256, 1, 1);

    // fused gather_max + pool2 (only 256 pooled rows)
    gather_max_pool_kernel<<<(BATCH * N3 * 64 + 255) / 256, 256>>>(fa, nb, pool2, fb, N2, N3, 256);
    gather_rows_kernel<<<(BATCH * N3 * 3 + 255) / 256, 256>>>(v2, pool2, v3, N2, N3, 3);

    // ================= stage 3 (256 pts) =================
    knn_kernel<<<dim3(N3 / 128, BATCH), 128>>>(v3, N3, nb);

    gemm128_kernel<<<dim3(16, BATCH * N3 / 128), 256>>>(fb, W4, b4, fo, BATCH * N3, 256, 2048);
    conv_act_kernel<<<BATCH * N3, 256>>>(v3, nb, nd4, fo, fa, N3, 1024, 1, 0);

    // ---- GeM -> y ----
    gem_kernel<<<(BATCH * 256 + 255) / 256, 256>>>(fa, gem_p, out);

    // ================= NetVLAD =================
    gemm_kahan_kernel<<<dim3(1, BATCH * N3 / 64), 256>>>(fa, cluster_w, act, BATCH * N3, 1024, 64);
    bn1_stats_kernel<<<64, 256>>>(act, bnm, bnv, BATCH * N3);
    bn_softmax_kernel<<<BATCH * N3, 64>>>(act, bnm, bnv, bn1_g, bn1_b);
    asum_kernel<<<2, 256>>>(act, asum);
    vlad_kernel<<<dim3(256, BATCH), 256>>>(act, fa, asum, cluster_w2, vlad);
    colnorm_kernel<<<BATCH, 1024>>>(vlad, cn);
    tn_kernel<<<1, 32>>>(cn, tn);
    vnorm_kernel<<<(BATCH * 1024 * 64 + 255) / 256, 256>>>(vlad, cn, tn);

    skinny8_kernel<<<dim3(4, 64), 256>>>(vlad, hidden_w, part, 65536, 1024);
    reduce_chunks_kernel<<<(BATCH * 1024 + 255) / 256, 256>>>(part, hidden, 64, BATCH * 1024);
    bn8_kernel<<<4, 256>>>(hidden, bn2_g, bn2_b, vbn, 1024);

    skinny8_kernel<<<dim3(4, 1), 256>>>(vbn, gating_w, part, 1024, 1024);
    reduce_chunks_kernel<<<(BATCH * 1024 + 255) / 256, 256>>>(part, gpre, 1, BATCH * 1024);
    gate_final_kernel<<<4, 256>>>(vbn, gpre, gbn_g, gbn_b, out + BATCH * 1024);
}

// round 5
// speedup vs baseline: 2.3916x; 1.0733x over previous
#include <cuda_runtime.h>
#include <math.h>
#include <stdint.h>

#define BATCH 8
#define KNNK 20
#define N1 4096
#define N2 1024
#define N3 256

// ======================= device scratch =======================
__device__ float g_fo[BATCH * 4096 * 128];
__device__ float g_fa[BATCH * 4096 * 64];
__device__ float g_fb[BATCH * 4096 * 64];
__device__ int   g_nb[BATCH * 4096 * KNNK];
__device__ float g_ndirs[1504 * 3];
__device__ int   g_pool1[1024];
__device__ int   g_pool2[256];
__device__ float g_v2[BATCH * 1024 * 3];
__device__ float g_v3[BATCH * 256 * 3];
__device__ float g_act[BATCH * 256 * 64];
__device__ float g_bnm[64];
__device__ float g_bnv[64];
__device__ float g_asum[BATCH * 64];
__device__ float g_vlad[BATCH * 1024 * 64];
__device__ float g_cn[BATCH * 64];
__device__ float g_tn[BATCH];
__device__ float g_part[64 * BATCH * 1024];
__device__ float g_vbn[BATCH * 1024];
__device__ float g_gpre[BATCH * 1024];

__device__ __forceinline__ void kadd(float& s, float& c, float v) {
    float y = __fadd_rn(v, -c);
    float t = __fadd_rn(s, y);
    c = __fadd_rn(__fadd_rn(t, -s), -y);
    s = t;
}

// ======================= pools =======================
struct PoolParams { int p1[1024]; int p2[256]; };

__global__ void set_pools_kernel(PoolParams pp) {
    for (int i = threadIdx.x; i < 1024; i += blockDim.x) g_pool1[i] = pp.p1[i];
    for (int i = threadIdx.x; i < 256;  i += blockDim.x) g_pool2[i] = pp.p2[i];
}

// ======================= direction normalizations =======================
__global__ void norm_dirs_all_kernel(const float* __restrict__ d0, const float* __restrict__ d1,
                                     const float* __restrict__ d2, const float* __restrict__ d3,
                                     const float* __restrict__ d4) {
    int t = blockIdx.x * blockDim.x + threadIdx.x;
    const float* src; int F, off, f;
    if      (t < 32)   { src = d0; F = 32;   off = 0;   f = t; }
    else if (t < 96)   { src = d1; F = 64;   off = 32;  f = t - 32; }
    else if (t < 224)  { src = d2; F = 128;  off = 96;  f = t - 96; }
    else if (t < 480)  { src = d3; F = 256;  off = 224; f = t - 224; }
    else if (t < 1504) { src = d4; F = 1024; off = 480; f = t - 480; }
    else return;
    float a = src[f], b = src[F + f], c = src[2 * F + f];
    float n = fmaxf(sqrtf(a * a + b * b + c * c), 1e-12f);
    g_ndirs[(off + f) * 3]     = a / n;
    g_ndirs[(off + f) * 3 + 1] = b / n;
    g_ndirs[(off + f) * 3 + 2] = c / n;
}

// ======================= KNN (4-way ILP on candidate distances) =======================
#define KNN_TILE 128
__global__ void knn_kernel(const float* __restrict__ v, int N, int* __restrict__ nb) {
    int b = blockIdx.y;
    int i = blockIdx.x * blockDim.x + threadIdx.x;
    const float* vb = v + (size_t)b * N * 3;
    float xi = vb[i * 3], yi = vb[i * 3 + 1], zi = vb[i * 3 + 2];
    float sqi = __fadd_rn(__fadd_rn(__fmul_rn(xi, xi), __fmul_rn(yi, yi)), __fmul_rn(zi, zi));

    float bd[KNNK]; int bi_[KNNK];
#pragma unroll
    for (int t = 0; t < KNNK; t++) { bd[t] = INFINITY; bi_[t] = 0x7fffffff; }
    float worst_d = INFINITY; int wslot = 0;

    __shared__ float4 sp[KNN_TILE];
    for (int base = 0; base < N; base += KNN_TILE) {
        {
            int t = threadIdx.x;
            float X = vb[(base + t) * 3], Y = vb[(base + t) * 3 + 1], Z = vb[(base + t) * 3 + 2];
            float S = __fadd_rn(__fadd_rn(__fmul_rn(X, X), __fmul_rn(Y, Y)), __fmul_rn(Z, Z));
            sp[t] = make_float4(X, Y, Z, S);
        }
        __syncthreads();
        for (int t = 0; t < KNN_TILE; t += 4) {
            float d4_[4];
#pragma unroll
            for (int u = 0; u < 4; u++) {
                float4 q = sp[t + u];
                float dot = fmaf(zi, q.z, fmaf(yi, q.y, __fmul_rn(xi, q.x)));
                d4_[u] = __fadd_rn(__fadd_rn(sqi, q.w), -__fmul_rn(2.f, dot));
            }
#pragma unroll
            for (int u = 0; u < 4; u++) {
                int j = base + t + u;
                float d = d4_[u];
                if (j != i && d < worst_d) {
#pragma unroll
                    for (int s = 0; s < KNNK; s++) if (s == wslot) { bd[s] = d; bi_[s] = j; }
                    worst_d = bd[0]; wslot = 0;
#pragma unroll
                    for (int s = 1; s < KNNK; s++) {
                        if (bd[s] > worst_d) { worst_d = bd[s]; wslot = s; }
                    }
                }
            }
        }
        __syncthreads();
    }
#pragma unroll
    for (int t = 0; t < KNNK; t++) nb[((size_t)b * N + i) * KNNK + t] = bi_[t];
}

// ======================= conv_surface =======================
__global__ void conv_surface_kernel(const float* __restrict__ v, const int* __restrict__ nb,
                                    const float* __restrict__ ndirs, float* __restrict__ fm,
                                    int N, int OC, int G) {
    __shared__ float sdx[160], sdy[160], sdz[160];
    int p0 = blockIdx.x * G;
    int t = threadIdx.x;
    if (t < G * KNNK) {
        int g = t / KNNK, k = t % KNNK;
        int p = p0 + g; int b = p / N; int n = p % N;
        const float* vb = v + (size_t)b * N * 3;
        int j = nb[(size_t)p * KNNK + k];
        float dx = vb[j * 3] - vb[n * 3];
        float dy = vb[j * 3 + 1] - vb[n * 3 + 1];
        float dz = vb[j * 3 + 2] - vb[n * 3 + 2];
        float nm = fmaxf(sqrtf(dx * dx + dy * dy + dz * dz), 1e-12f);
        sdx[t] = dx / nm; sdy[t] = dy / nm; sdz[t] = dz / nm;
    }
    __syncthreads();
    int OCc = 256 / G;
    int g = t / OCc, f = t % OCc;
    int p = p0 + g;
    float d0 = ndirs[f * 3], d1 = ndirs[f * 3 + 1], d2 = ndirs[f * 3 + 2];
    float m = 0.f;
    int kb = g * KNNK;
#pragma unroll
    for (int k = 0; k < KNNK; k++) {
        float th = fmaxf(sdx[kb + k] * d0 + sdy[kb + k] * d1 + sdz[kb + k] * d2, 0.f);
        m = fmaxf(m, th);
    }
    fm[(size_t)p * OC + f] = m;
}

// ======================= conv_layer activation =======================
__global__ void conv_act_kernel(const float* __restrict__ v, const int* __restrict__ nb,
                                const float* __restrict__ ndirs, const float* __restrict__ fo,
                                float* __restrict__ out, int N, int OC, int G, int relu_out) {
    int C = 2 * OC;
    __shared__ float sdx[160], sdy[160], sdz[160];
    __shared__ int sj[160];
    int p0 = blockIdx.x * G;
    int t = threadIdx.x;
    if (t < G * KNNK) {
        int g = t / KNNK, k = t % KNNK;
        int p = p0 + g; int b = p / N; int n = p % N;
        const float* vb = v + (size_t)b * N * 3;
        int j = nb[(size_t)p * KNNK + k];
        sj[t] = b * N + j;
        float dx = vb[j * 3] - vb[n * 3];
        float dy = vb[j * 3 + 1] - vb[n * 3 + 1];
        float dz = vb[j * 3 + 2] - vb[n * 3 + 2];
        float nm = fmaxf(sqrtf(dx * dx + dy * dy + dz * dz), 1e-12f);
        sdx[t] = dx / nm; sdy[t] = dy / nm; sdz[t] = dz / nm;
    }
    __syncthreads();
    int OCc = 256 / G;
    int g = t / OCc, fb = t % OCc;
    int p = p0 + g;
    int kb = g * KNNK;
    const float* forow = fo + (size_t)p * C;
    for (int f = fb; f < OC; f += OCc) {
        float d0 = ndirs[f * 3], d1 = ndirs[f * 3 + 1], d2 = ndirs[f * 3 + 2];
        float m = -INFINITY;
#pragma unroll
        for (int k = 0; k < KNNK; k++) {
            float th = fmaxf(sdx[kb + k] * d0 + sdy[kb + k] * d1 + sdz[kb + k] * d2, 0.f);
            float fs = fo[(size_t)sj[kb + k] * C + OC + f];
            m = fmaxf(m, th * fs);
        }
        float val = forow[f] + m;
        if (relu_out) val = fmaxf(val, 0.f);
        out[(size_t)p * OC + f] = val;
    }
}

// ======================= fused gather_max + pool =======================
__global__ void gather_max_pool_kernel(const float* __restrict__ fm, const int* __restrict__ nb,
                                       const int* __restrict__ pool, float* __restrict__ out,
                                       int Nin, int Nout, int F) {
    int F4 = F / 4;
    int idx = blockIdx.x * blockDim.x + threadIdx.x;
    int tot = BATCH * Nout * F4;
    if (idx >= tot) return;
    int f4 = idx % F4; int r = idx / F4; int b = r / Nout; int pp = r % Nout;
    int row = pool[pp];
    const int* nbp = nb + ((size_t)b * Nin + row) * KNNK;
    float4 m = make_float4(-INFINITY, -INFINITY, -INFINITY, -INFINITY);
#pragma unroll
    for (int k = 0; k < KNNK; k++) {
        const float4 vv = *(const float4*)&fm[((size_t)b * Nin + nbp[k]) * F + f4 * 4];
        m.x = fmaxf(m.x, vv.x); m.y = fmaxf(m.y, vv.y);
        m.z = fmaxf(m.z, vv.z); m.w = fmaxf(m.w, vv.w);
    }
    *(float4*)&out[(size_t)r * F + f4 * 4] = m;
}

__global__ void gather_rows_kernel(const float* __restrict__ in, const int* __restrict__ pool,
                                   float* __restrict__ out, int Nin, int Nout, int F) {
    int idx = blockIdx.x * blockDim.x + threadIdx.x;
    int tot = BATCH * Nout * F;
    if (idx >= tot) return;
    int f = idx % F; int r = idx / F; int b = r / Nout; int pp = r % Nout;
    out[idx] = in[((size_t)b * Nin + pool[pp]) * F + f];
}

// ======================= 128x128 SGEMM =======================
#define GT 132
__global__ __launch_bounds__(256, 2) void gemm128_kernel(
        const float* __restrict__ A, const float* __restrict__ B,
        const float* __restrict__ bias, float* __restrict__ C,
        int M, int K, int N) {
    __shared__ float As[8][GT];
    __shared__ float Bs[8][GT];
    int row0 = blockIdx.y * 128, col0 = blockIdx.x * 128;
    int tid = threadIdx.x;
    int tx = tid % 16, ty = tid / 16;
    int arow = tid >> 1, acol = (tid & 1) * 4;
    int brow = tid >> 5, bcol = (tid & 31) * 4;
    float4 pa = *(const float4*)&A[(size_t)(row0 + arow) * K + acol];
    float4 pb = *(const float4*)&B[(size_t)brow * N + col0 + bcol];
    float acc[8][8] = {};
    for (int k0 = 0; k0 < K; k0 += 8) {
        As[acol][arow] = pa.x; As[acol + 1][arow] = pa.y;
        As[acol + 2][arow] = pa.z; As[acol + 3][arow] = pa.w;
        *(float4*)&Bs[brow][bcol] = pb;
        __syncthreads();
        if (k0 + 8 < K) {
            pa = *(const float4*)&A[(size_t)(row0 + arow) * K + k0 + 8 + acol];
            pb = *(const float4*)&B[(size_t)(k0 + 8 + brow) * N + col0 + bcol];
        }
#pragma unroll
        for (int kk = 0; kk < 8; kk++) {
            float a[8], bb[8];
            *(float4*)&a[0] = *(const float4*)&As[kk][ty * 8];
            *(float4*)&a[4] = *(const float4*)&As[kk][ty * 8 + 4];
            *(float4*)&bb[0] = *(const float4*)&Bs[kk][tx * 8];
            *(float4*)&bb[4] = *(const float4*)&Bs[kk][tx * 8 + 4];
#pragma unroll
            for (int i = 0; i < 8; i++)
#pragma unroll
                for (int j = 0; j < 8; j++) acc[i][j] = fmaf(a[i], bb[j], acc[i][j]);
        }
        __syncthreads();
    }
    float bz[8];
    if (bias) {
        *(float4*)&bz[0] = *(const float4*)&bias[col0 + tx * 8];
        *(float4*)&bz[4] = *(const float4*)&bias[col0 + tx * 8 + 4];
    } else {
#pragma unroll
        for (int j = 0; j < 8; j++) bz[j] = 0.f;
    }
#pragma unroll
    for (int i = 0; i < 8; i++) {
        float* crow = &C[(size_t)(row0 + ty * 8 + i) * N + col0 + tx * 8];
        float4 r0 = make_float4(acc[i][0] + bz[0], acc[i][1] + bz[1], acc[i][2] + bz[2], acc[i][3] + bz[3]);
        float4 r1 = make_float4(acc[i][4] + bz[4], acc[i][5] + bz[5], acc[i][6] + bz[6], acc[i][7] + bz[7]);
        *(float4*)crow = r0;
        *(float4*)(crow + 4) = r1;
    }
}

// ======================= cluster GEMM, tile-compensated =======================
__global__ void gemm_kahan_kernel(const float* __restrict__ A, const float* __restrict__ B,
                                  float* __restrict__ C, int M, int K, int N) {
    __shared__ float As[16][68];
    __shared__ float Bs[16][68];
    int row0 = blockIdx.y * 64, col0 = blockIdx.x * 64;
    int tid = threadIdx.x;
    int tx = tid % 16, ty = tid / 16;
    float acc[4][4] = {}; float cmp[4][4] = {};
    int ar = tid >> 2, ac4 = (tid & 3) * 4;
    int br = tid >> 4, bc4 = (tid & 15) * 4;
    for (int k0 = 0; k0 < K; k0 += 16) {
        float4 av = *(const float4*)&A[(size_t)(row0 + ar) * K + k0 + ac4];
        As[ac4][ar] = av.x; As[ac4 + 1][ar] = av.y; As[ac4 + 2][ar] = av.z; As[ac4 + 3][ar] = av.w;
        *(float4*)&Bs[br][bc4] = *(const float4*)&B[(size_t)(k0 + br) * N + col0 + bc4];
        __syncthreads();
        float tacc[4][4] = {};   // plain FMA within 16-deep tile
#pragma unroll
        for (int kk = 0; kk < 16; kk++) {
            float a[4], bb[4];
            float4 a4 = *(const float4*)&As[kk][ty * 4];
            float4 b4 = *(const float4*)&Bs[kk][tx * 4];
            a[0] = a4.x; a[1] = a4.y; a[2] = a4.z; a[3] = a4.w;
            bb[0] = b4.x; bb[1] = b4.y; bb[2] = b4.z; bb[3] = b4.w;
#pragma unroll
            for (int i = 0; i < 4; i++)
#pragma unroll
                for (int j = 0; j < 4; j++) tacc[i][j] = fmaf(a[i], bb[j], tacc[i][j]);
        }
#pragma unroll
        for (int i = 0; i < 4; i++)
#pragma unroll
            for (int j = 0; j < 4; j++) kadd(acc[i][j], cmp[i][j], tacc[i][j]);
        __syncthreads();
    }
#pragma unroll
    for (int i = 0; i < 4; i++)
#pragma unroll
        for (int j = 0; j < 4; j++)
            C[(size_t)(row0 + ty * 4 + i) * N + col0 + tx * 4 + j] = acc[i][j];
}

// ======================= GeM: split into 8 chunks for parallelism =======================
__device__ __forceinline__ float fast_pow(float x, float p) {
    return exp2f(p * log2f(x));
}
// grid (8 chunks, BATCH), block 256; part layout [nc][b][1024]
__global__ void gem_part_kernel(const float* __restrict__ fm4, const float* __restrict__ gem_p,
                                float* __restrict__ part) {
    int nc = blockIdx.x, b = blockIdx.y;
    int c4 = threadIdx.x * 4;
    float p = gem_p[0];
    bool p3 = (p == 3.0f);
    float s[4] = {};
    for (int n = nc * 32; n < nc * 32 + 32; n++) {
        float4 f = *(const float4*)&fm4[((size_t)b * N3 + n) * 1024 + c4];
        float fx = fmaxf(f.x, 1e-6f), fy = fmaxf(f.y, 1e-6f);
        float fz = fmaxf(f.z, 1e-6f), fw = fmaxf(f.w, 1e-6f);
        if (p3) {
            s[0] = __fadd_rn(s[0], fx * fx * fx);
            s[1] = __fadd_rn(s[1], fy * fy * fy);
            s[2] = __fadd_rn(s[2], fz * fz * fz);
            s[3] = __fadd_rn(s[3], fw * fw * fw);
        } else {
            s[0] = __fadd_rn(s[0], fast_pow(fx, p));
            s[1] = __fadd_rn(s[1], fast_pow(fy, p));
            s[2] = __fadd_rn(s[2], fast_pow(fz, p));
            s[3] = __fadd_rn(s[3], fast_pow(fw, p));
        }
    }
    *(float4*)&part[((size_t)nc * BATCH + b) * 1024 + c4] = make_float4(s[0], s[1], s[2], s[3]);
}

__global__ void gem_merge_kernel(const float* __restrict__ part, const float* __restrict__ gem_p,
                                 float* __restrict__ y) {
    int idx = blockIdx.x * blockDim.x + threadIdx.x;
    if (idx >= BATCH * 1024) return;
    int b = idx / 1024, c = idx % 1024;
    float p = gem_p[0];
    float s = 0.f, sc = 0.f;
    for (int nc = 0; nc < 8; nc++) kadd(s, sc, part[((size_t)nc * BATCH + b) * 1024 + c]);
    s /= (float)N3;
    y[idx] = (p == 3.0f) ? cbrtf(s) : fast_pow(s, 1.f / p);
}

// ======================= NetVLAD =======================
__global__ void bn1_stats_kernel(const float* __restrict__ act, float* __restrict__ mean,
                                 float* __restrict__ var, int rows) {
    int k = blockIdx.x;
    __shared__ double sd[256];
    float a = 0.f, ac = 0.f;
    for (int r = threadIdx.x; r < rows; r += 256) kadd(a, ac, act[(size_t)r * 64 + k]);
    sd[threadIdx.x] = (double)a; __syncthreads();
    for (int s = 128; s > 0; s >>= 1) {
        if (threadIdx.x < s) sd[threadIdx.x] += sd[threadIdx.x + s];
        __syncthreads();
    }
    float m = (float)(sd[0] / rows);
    __syncthreads();
    float q = 0.f, qc = 0.f;
    for (int r = threadIdx.x; r < rows; r += 256) {
        float d = __fadd_rn(act[(size_t)r * 64 + k], -m);
        kadd(q, qc, __fmul_rn(d, d));
    }
    sd[threadIdx.x] = (double)q; __syncthreads();
    for (int s = 128; s > 0; s >>= 1) {
        if (threadIdx.x < s) sd[threadIdx.x] += sd[threadIdx.x + s];
        __syncthreads();
    }
    if (threadIdx.x == 0) { mean[k] = m; var[k] = (float)(sd[0] / rows); }
}

__global__ void bn_softmax_kernel(float* __restrict__ act, const float* __restrict__ mean,
                                  const float* __restrict__ var, const float* __restrict__ g,
                                  const float* __restrict__ bb) {
    int r = blockIdx.x; int k = threadIdx.x;
    __shared__ float sv[64];
    float v = (act[(size_t)r * 64 + k] - mean[k]) * rsqrtf(var[k] + 1e-5f) * g[k] + bb[k];
    sv[k] = v; __syncthreads();
    float mx = -INFINITY;
    for (int t = 0; t < 64; t++) mx = fmaxf(mx, sv[t]);
    float e = expf(v - mx);
    __syncthreads(); sv[k] = e; __syncthreads();
    float s = 0.f, sc = 0.f;
    for (int t = 0; t < 64; t++) kadd(s, sc, sv[t]);
    act[(size_t)r * 64 + k] = e / s;
}

__global__ void asum_kernel(const float* __restrict__ act, float* __restrict__ asum) {
    int t = blockIdx.x * blockDim.x + threadIdx.x;
    if (t >= BATCH * 64) return;
    int b = t / 64, k = t % 64;
    float s = 0.f, sc = 0.f;
    for (int m0 = 0; m0 < N3; m0 += 32) {
        float bs = 0.f;
#pragma unroll 8
        for (int m = m0; m < m0 + 32; m++) bs = __fadd_rn(bs, act[((size_t)b * N3 + m) * 64 + k]);
        kadd(s, sc, bs);
    }
    asum[t] = s;
}

// block-compensated vlad einsum
__global__ void vlad_kernel(const float* __restrict__ act, const float* __restrict__ xv,
                            const float* __restrict__ asum, const float* __restrict__ cw2,
                            float* __restrict__ vlad) {
    int b = blockIdx.y;
    int k = threadIdx.x % 64;
    int f = blockIdx.x * 4 + threadIdx.x / 64;
    float s = 0.f, sc = 0.f;
    for (int m0 = 0; m0 < N3; m0 += 32) {
        float bs = 0.f;
#pragma unroll 8
        for (int m = m0; m < m0 + 32; m++) {
            bs = fmaf(act[((size_t)b * N3 + m) * 64 + k], xv[((size_t)b * N3 + m) * 1024 + f], bs);
        }
        kadd(s, sc, bs);
    }
    s = __fadd_rn(s, -__fmul_rn(asum[b * 64 + k], cw2[(size_t)f * 64 + k]));
    vlad[((size_t)b * 1024 + f) * 64 + k] = s;
}

__global__ void colnorm_kernel(const float* __restrict__ vlad, float* __restrict__ cn) {
    int b = blockIdx.x; int tid = threadIdx.x;
    int k = tid % 64, grp = tid / 64;
    float s = 0.f, sc = 0.f;
    for (int q0 = 0; q0 < 64; q0 += 16) {
        float bs = 0.f;
#pragma unroll
        for (int q = q0; q < q0 + 16; q++) {
            int f = grp + q * 16;
            float v = vlad[((size_t)b * 1024 + f) * 64 + k];
            bs = fmaf(v, v, bs);
        }
        kadd(s, sc, bs);
    }
    __shared__ double sm[1024];
    sm[tid] = (double)s; __syncthreads();
    if (grp == 0) {
        double t = 0.0;
        for (int g2 = 0; g2 < 16; g2++) t += sm[g2 * 64 + k];
        cn[b * 64 + k] = (float)t;
    }
}

__global__ void tn_kernel(const float* __restrict__ cn, float* __restrict__ tn) {
    int b = threadIdx.x;
    if (b >= BATCH) return;
    double s = 0.0;
    for (int k = 0; k < 64; k++) {
        float c = cn[b * 64 + k];
        float d = fmaxf(sqrtf(c), 1e-12f);
        s += (double)(c / (d * d));
    }
    tn[b] = (float)s;
}

__global__ void vnorm_kernel(float* __restrict__ vlad, const float* __restrict__ cn,
                             const float* __restrict__ tn) {
    int idx = blockIdx.x * blockDim.x + threadIdx.x;
    if (idx >= BATCH * 1024 * 64) return;
    int k = idx % 64; int b = idx / (1024 * 64);
    float d1 = fmaxf(sqrtf(cn[b * 64 + k]), 1e-12f);
    float d2 = fmaxf(sqrtf(tn[b]), 1e-12f);
    vlad[idx] = vlad[idx] / d1 / d2;
}

// block-compensated skinny GEMM: part[chunk][b][j]
#define SKC 1024
__global__ void skinny8_kernel(const float* __restrict__ A, const float* __restrict__ W,
                               float* __restrict__ part, int K, int N) {
    int j = blockIdx.x * 256 + threadIdx.x;
    int k0 = blockIdx.y * SKC;
    int len = min(SKC, K - k0);
    __shared__ float xs[BATCH * SKC];
    for (int t = threadIdx.x; t < BATCH * len; t += 256) {
        int bb = t / len; int ii = t % len;
        xs[bb * len + ii] = A[(size_t)bb * K + k0 + ii];
    }
    __syncthreads();
    if (j < N) {
        float acc[BATCH] = {}; float cmp[BATCH] = {};
#pragma unroll 1
        for (int i0 = 0; i0 < len; i0 += 16) {
            float ba[BATCH] = {};
#pragma unroll 4
            for (int i = i0; i < i0 + 16; i++) {
                float w = W[(size_t)(k0 + i) * N + j];
#pragma unroll
                for (int bb = 0; bb < BATCH; bb++) ba[bb] = fmaf(xs[bb * len + i], w, ba[bb]);
            }
#pragma unroll
            for (int bb = 0; bb < BATCH; bb++) kadd(acc[bb], cmp[bb], ba[bb]);
        }
#pragma unroll
        for (int bb = 0; bb < BATCH; bb++) {
            part[(size_t)blockIdx.y * BATCH * N + bb * N + j] = acc[bb];
        }
    }
}

// bn8 reading chunked partials directly (fuses reduce_chunks)
__global__ void bn8_from_part_kernel(const float* __restrict__ part, const float* __restrict__ g,
                                     const float* __restrict__ bb, float* __restrict__ out,
                                     int nchunks, int N) {
    int j = blockIdx.x * blockDim.x + threadIdx.x;
    if (j >= N) return;
    float h[BATCH];
#pragma unroll
    for (int b = 0; b < BATCH; b++) {
        float s = 0.f, sc = 0.f;
        for (int c = 0; c < nchunks; c++) kadd(s, sc, part[(size_t)c * BATCH * N + b * N + j]);
        h[b] = s;
    }
    double m = 0.0;
#pragma unroll
    for (int b = 0; b < BATCH; b++) m += (double)h[b];
    m /= BATCH;
    double q = 0.0;
#pragma unroll
    for (int b = 0; b < BATCH; b++) { double d = (double)h[b] - m; q += d * d; }
    q /= BATCH;
    float mf = (float)m;
    float inv = rsqrtf((float)q + 1e-5f);
#pragma unroll
    for (int b = 0; b < BATCH; b++) out[b * N + j] = (h[b] - mf) * inv * g[j] + bb[j];
}

// gate BN + sigmoid + multiply, reading gating partials directly (1 chunk)
__global__ void gate_final_kernel(const float* __restrict__ vbn, const float* __restrict__ gpre,
                                  const float* __restrict__ gg, const float* __restrict__ gb,
                                  float* __restrict__ desc) {
    int j = blockIdx.x * blockDim.x + threadIdx.x;
    if (j >= 1024) return;
    double m = 0.0;
    for (int b = 0; b < BATCH; b++) m += (double)gpre[b * 1024 + j];
    m /= BATCH;
    double q = 0.0;
    for (int b = 0; b < BATCH; b++) { double d = (double)gpre[b * 1024 + j] - m; q += d * d; }
    q /= BATCH;
    float mf = (float)m;
    float inv = rsqrtf((float)q + 1e-5f);
    for (int b = 0; b < BATCH; b++) {
        float z = (gpre[b * 1024 + j] - mf) * inv * gg[j] + gb[j];
        float s = 1.f / (1.f + expf(-z));
        desc[b * 1024 + j] = vbn[b * 1024 + j] * s;
    }
}

// ======================= host: numpy-compatible MT19937 pools =======================
struct MTState { uint32_t mt[624]; int idx; };

static void mt_seed(MTState& s, uint32_t seed) {
    for (int p = 0; p < 624; p++) {
        s.mt[p] = seed;
        seed = 1812433253u * (seed ^ (seed >> 30)) + (uint32_t)p + 1u;
    }
    s.idx = 624;
}
static uint32_t mt_next(MTState& s) {
    if (s.idx >= 624) {
        for (int i = 0; i < 624; i++) {
            uint32_t y = (s.mt[i] & 0x80000000u) | (s.mt[(i + 1) % 624] & 0x7fffffffu);
            uint32_t v = s.mt[(i + 397) % 624] ^ (y >> 1);
            if (y & 1u) v ^= 0x9908b0dfu;
            s.mt[i] = v;
        }
        s.idx = 0;
    }
    uint32_t y = s.mt[s.idx++];
    y ^= y >> 11;
    y ^= (y << 7) & 0x9d2c5680u;
    y ^= (y << 15) & 0xefc60000u;
    y ^= y >> 18;
    return y;
}
static uint32_t rk_interval(MTState& s, uint32_t mx) {
    if (mx == 0) return 0;
    uint32_t mask = mx;
    mask |= mask >> 1; mask |= mask >> 2; mask |= mask >> 4;
    mask |= mask >> 8; mask |= mask >> 16;
    uint32_t v;
    while ((v = (mt_next(s) & mask)) > mx) {}
    return v;
}
static void np_permutation(uint32_t seed, int n, int* out) {
    for (int i = 0; i < n; i++) out[i] = i;
    MTState s; mt_seed(s, seed);
    for (int i = n - 1; i >= 1; i--) {
        uint32_t j = rk_interval(s, (uint32_t)i);
        int t = out[i]; out[i] = out[(int)j]; out[(int)j] = t;
    }
}

// ======================= launch =======================
extern "C" void kernel_launch(void* const* d_in, const int* in_sizes, int n_in,
                              void* d_out, int out_size) {
    const float* x         = (const float*)d_in[0];
    const float* dir0      = (const float*)d_in[1];
    const float* W1        = (const float*)d_in[2];
    const float* b1        = (const float*)d_in[3];
    const float* dir1      = (const float*)d_in[4];
    const float* W2        = (const float*)d_in[5];
    const float* b2        = (const float*)d_in[6];
    const float* dir2      = (const float*)d_in[7];
    const float* W3        = (const float*)d_in[8];
    const float* b3        = (const float*)d_in[9];
    const float* dir3      = (const float*)d_in[10];
    const float* W4        = (const float*)d_in[11];
    const float* b4        = (const float*)d_in[12];
    const float* dir4      = (const float*)d_in[13];
    const float* gem_p     = (const float*)d_in[14];
    const float* cluster_w = (const float*)d_in[15];
    const float* cluster_w2= (const float*)d_in[16];
    const float* hidden_w  = (const float*)d_in[17];
    const float* bn1_g     = (const float*)d_in[18];
    const float* bn1_b     = (const float*)d_in[19];
    const float* bn2_g     = (const float*)d_in[20];
    const float* bn2_b     = (const float*)d_in[21];
    const float* gating_w  = (const float*)d_in[22];
    const float* gbn_g     = (const float*)d_in[23];
    const float* gbn_b     = (const float*)d_in[24];
    float* out = (float*)d_out;

    float *fo, *fa, *fb, *ndirs, *v2, *v3, *act, *bnm, *bnv, *asum, *vlad, *cn, *tn, *part, *vbn, *gpre;
    int *nb, *pool1, *pool2;
    cudaGetSymbolAddress((void**)&fo, g_fo);
    cudaGetSymbolAddress((void**)&fa, g_fa);
    cudaGetSymbolAddress((void**)&fb, g_fb);
    cudaGetSymbolAddress((void**)&nb, g_nb);
    cudaGetSymbolAddress((void**)&ndirs, g_ndirs);
    cudaGetSymbolAddress((void**)&pool1, g_pool1);
    cudaGetSymbolAddress((void**)&pool2, g_pool2);
    cudaGetSymbolAddress((void**)&v2, g_v2);
    cudaGetSymbolAddress((void**)&v3, g_v3);
    cudaGetSymbolAddress((void**)&act, g_act);
    cudaGetSymbolAddress((void**)&bnm, g_bnm);
    cudaGetSymbolAddress((void**)&bnv, g_bnv);
    cudaGetSymbolAddress((void**)&asum, g_asum);
    cudaGetSymbolAddress((void**)&vlad, g_vlad);
    cudaGetSymbolAddress((void**)&cn, g_cn);
    cudaGetSymbolAddress((void**)&tn, g_tn);
    cudaGetSymbolAddress((void**)&part, g_part);
    cudaGetSymbolAddress((void**)&vbn, g_vbn);
    cudaGetSymbolAddress((void**)&gpre, g_gpre);

    static PoolParams pp;
    {
        static int perm1[N1];
        static int perm2[N2];
        np_permutation(1u, N1, perm1);
        np_permutation(2u, N2, perm2);
        for (int i = 0; i < 1024; i++) pp.p1[i] = perm1[i];
        for (int i = 0; i < 256;  i++) pp.p2[i] = perm2[i];
    }
    set_pools_kernel<<<1, 256>>>(pp);
    norm_dirs_all_kernel<<<6, 256>>>(dir0, dir1, dir2, dir3, dir4);

    const float* nd0 = ndirs;
    const float* nd1 = ndirs + 32 * 3;
    const float* nd2 = ndirs + 96 * 3;
    const float* nd3 = ndirs + 224 * 3;
    const float* nd4 = ndirs + 480 * 3;

    // ================= stage 1 (4096 pts) =================
    knn_kernel<<<dim3(N1 / 128, BATCH), 128>>>(x, N1, nb);
    conv_surface_kernel<<<BATCH * N1 / 8, 256>>>(x, nb, nd0, fa, N1, 32, 8);

    gemm128_kernel<<<dim3(1, BATCH * N1 / 128), 256>>>(fa, W1, b1, fo, BATCH * N1, 32, 128);
    conv_act_kernel<<<BATCH * N1 / 4, 256>>>(x, nb, nd1, fo, fb, N1, 64, 4, 1);

    gather_max_pool_kernel<<<(BATCH * N2 * 16 + 255) / 256, 256>>>(fb, nb, pool1, fa, N1, N2, 64);
    gather_rows_kernel<<<(BATCH * N2 * 3 + 255) / 256, 256>>>(x, pool1, v2, N1, N2, 3);

    // ================= stage 2 (1024 pts) =================
    knn_kernel<<<dim3(N2 / 128, BATCH), 128>>>(v2, N2, nb);

    gemm128_kernel<<<dim3(2, BATCH * N2 / 128), 256>>>(fa, W2, b2, fo, BATCH * N2, 64, 256);
    conv_act_kernel<<<BATCH * N2 / 2, 256>>>(v2, nb, nd2, fo, fb, N2, 128, 2, 1);

    gemm128_kernel<<<dim3(4, BATCH * N2 / 128), 256>>>(fb, W3, b3, fo, BATCH * N2, 128, 512);
    conv_act_kernel<<<BATCH * N2, 256>>>(v2, nb, nd3, fo, fa, N2, 256, 1, 1);

    gather_max_pool_kernel<<<(BATCH * N3 * 64 + 255) / 256, 256>>>(fa, nb, pool2, fb, N2, N3, 256);
    gather_rows_kernel<<<(BATCH * N3 * 3 + 255) / 256, 256>>>(v2, pool2, v3, N2, N3, 3);

    // ================= stage 3 (256 pts) =================
    knn_kernel<<<dim3(N3 / 128, BATCH), 128>>>(v3, N3, nb);

    gemm128_kernel<<<dim3(16, BATCH * N3 / 128), 256>>>(fb, W4, b4, fo, BATCH * N3, 256, 2048);
    conv_act_kernel<<<BATCH * N3, 256>>>(v3, nb, nd4, fo, fa, N3, 1024, 1, 0);

    // ---- GeM -> y ----
    gem_part_kernel<<<dim3(8, BATCH), 256>>>(fa, gem_p, part);
    gem_merge_kernel<<<(BATCH * 1024 + 255) / 256, 256>>>(part, gem_p, out);

    // ================= NetVLAD =================
    gemm_kahan_kernel<<<dim3(1, BATCH * N3 / 64), 256>>>(fa, cluster_w, act, BATCH * N3, 1024, 64);
    bn1_stats_kernel<<<64, 256>>>(act, bnm, bnv, BATCH * N3);
    bn_softmax_kernel<<<BATCH * N3, 64>>>(act, bnm, bnv, bn1_g, bn1_b);
    asum_kernel<<<2, 256>>>(act, asum);
    vlad_kernel<<<dim3(256, BATCH), 256>>>(act, fa, asum, cluster_w2, vlad);
    colnorm_kernel<<<BATCH, 1024>>>(vlad, cn);
    tn_kernel<<<1, 32>>>(cn, tn);
    vnorm_kernel<<<(BATCH * 1024 * 64 + 255) / 256, 256>>>(vlad, cn, tn);

    // hidden: 64 chunked partials, then fused reduce+bn2
    skinny8_kernel<<<dim3(4, 64), 256>>>(vlad, hidden_w, part, 65536, 1024);
    bn8_from_part_kernel<<<4, 256>>>(part, bn2_g, bn2_b, vbn, 64, 1024);

    // gating: single chunk -> gpre partials ARE the result
    skinny8_kernel<<<dim3(4, 1), 256>>>(vbn, gating_w, gpre, 1024, 1024);
    gate_final_kernel<<<4, 256>>>(vbn, gpre, gbn_g, gbn_b, out + BATCH * 1024);
}